// round 8
// baseline (speedup 1.0000x reference)
#include <cuda_runtime.h>
#include <math.h>

#define MAXB 16384

// ---------------- device scratch (no allocations allowed) ----------------
__device__ unsigned g_lut[3 * 512 * 8];    // [ (ch*512+key)*8 + g ]: five 6-bit slots/word (g<7), word 7 = pad
__device__ unsigned g_w2[288];             // [oc*9 + dy*3+dx], bit = input channel
__device__ int      g_T2[32];
__device__ unsigned g_w3[576];             // [oc*9 + dy*3+dx], bit = input channel
__device__ int      g_T3[64];
__device__ unsigned g_fc1[256];            // [j*2 + half], bit k = sign(w_fc1[j][half*32+k])
__device__ float    g_a4[128], g_c4[128];  // bn4 folded: h = clamp(a*s + c)
__device__ float    g_head[12];            // a5[2], c5[2], a6[4], c6[4]

// ---------------- bn threshold helper ----------------
__device__ __forceinline__ double bn_thresh_t(const float* bn, int C, int c) {
    // bn rows: gamma, beta, mean, var.  sign(bn(s)) >= 0  <=>  s >= m - b*sqrt(v+eps)/g   (g > 0)
    double g = bn[c], b = bn[C + c], m = bn[2 * C + c], v = bn[3 * C + c];
    return m - b * sqrt(v + 1e-5) / g;
}

// ---------------- prep: weight packing + thresholds + conv1 LUT (8 CTAs) ----------------
__global__ void prep_kernel(const float* __restrict__ w1, const float* __restrict__ w2,
                            const float* __restrict__ w3, const float* __restrict__ wfc1,
                            const float* __restrict__ bn1, const float* __restrict__ bn2,
                            const float* __restrict__ bn3, const float* __restrict__ bn4,
                            const float* __restrict__ bn5, const float* __restrict__ bn6) {
    __shared__ unsigned s_wc[96];   // [ch*32+oc]: 9-bit channel slice of w1
    __shared__ int      s_off[32];  // 31 - clamp(T1, -5, 31)

    const int t = blockIdx.x * 256 + threadIdx.x;
    const int nt = 8 * 256;

    if (threadIdx.x < 96) {
        int ch = threadIdx.x / 32, oc = threadIdx.x & 31;
        unsigned w = 0;
        for (int k = 0; k < 9; ++k)
            if (w1[oc * 27 + ch * 9 + k] >= 0.f) w |= 1u << k;
        s_wc[threadIdx.x] = w;
    }
    if (threadIdx.x < 32) {
        int oc = threadIdx.x;
        int T = (int)floor((27.0 - bn_thresh_t(bn1, 32, oc)) * 0.5);  // keep iff cnt <= T
        if (T < -5) T = -5;
        if (T > 31) T = 31;
        s_off[oc] = 31 - T;   // reject iff cnt + off >= 32
    }
    __syncthreads();

    // conv1 LUT: 1536 records of 8 words (7 data + 1 pad)
    for (int i = t; i < 1536; i += nt) {
        int ch = i / 512, key = i & 511;
        for (int g = 0; g < 7; ++g) {
            unsigned word = 0;
            for (int j = 0; j < 5; ++j) {
                int oc = 5 * g + j;
                if (oc < 32) {
                    unsigned f = (unsigned)__popc((key ^ s_wc[ch * 32 + oc]) & 0x1FF);
                    if (ch == 2) f += (unsigned)s_off[oc];
                    word |= f << (6 * j);
                }
            }
            g_lut[(ch * 512 + key) * 8 + g] = word;
        }
        g_lut[(ch * 512 + key) * 8 + 7] = 0;
    }

    for (int oc = t; oc < 32; oc += nt)
        g_T2[oc] = (int)floor((288.0 - bn_thresh_t(bn2, 32, oc)) * 0.5);
    for (int i = t; i < 288; i += nt) {
        int oc = i / 9, p = i % 9; unsigned w = 0;
        for (int c = 0; c < 32; ++c) if (w2[(oc * 32 + c) * 9 + p] >= 0.f) w |= 1u << c;
        g_w2[i] = w;
    }
    for (int i = t; i < 576; i += nt) {
        int oc = i / 9, p = i % 9; unsigned w = 0;
        for (int c = 0; c < 32; ++c) if (w3[(oc * 32 + c) * 9 + p] >= 0.f) w |= 1u << c;
        g_w3[i] = w;
    }
    for (int oc = t; oc < 64; oc += nt)
        g_T3[oc] = (int)floor((288.0 - bn_thresh_t(bn3, 64, oc)) * 0.5);
    for (int i = t; i < 256; i += nt) {
        int j = i >> 1, h = i & 1; unsigned w = 0;
        for (int k = 0; k < 32; ++k) if (wfc1[j * 64 + h * 32 + k] >= 0.f) w |= 1u << k;
        g_fc1[i] = w;
    }
    for (int j = t; j < 128; j += nt) {
        float g = bn4[j], b = bn4[128 + j], m = bn4[256 + j], v = bn4[384 + j];
        float inv = g * rsqrtf(v + 1e-5f);
        g_a4[j] = inv; g_c4[j] = b - m * inv;
    }
    if (t < 2) {
        float g = bn5[t], b = bn5[2 + t], m = bn5[4 + t], v = bn5[6 + t];
        float inv = g * rsqrtf(v + 1e-5f);
        g_head[t] = inv; g_head[2 + t] = b - m * inv;
    }
    if (t >= 4 && t < 8) {
        int q = t - 4;
        float g = bn6[q], b = bn6[4 + q], m = bn6[8 + q], v = bn6[12 + q];
        float inv = g * rsqrtf(v + 1e-5f);
        g_head[4 + q] = inv; g_head[8 + q] = b - m * inv;
    }
}

// naive 9-word popcount sum
__device__ __forceinline__ int popc9(unsigned x0, unsigned x1, unsigned x2,
                                     unsigned x3, unsigned x4, unsigned x5,
                                     unsigned x6, unsigned x7, unsigned x8) {
    return __popc(x0) + __popc(x1) + __popc(x2)
         + __popc(x3) + __popc(x4) + __popc(x5)
         + __popc(x6) + __popc(x7) + __popc(x8);
}

// dynamic smem word offsets (256-thread CTA, 32 samples)
#define SM_LUT  0                       // 12288 words (3*512*8)
#define SM_PIN  12288                   // 32*66 = 2112
#define SM_S1   14400                   // 32*100 = 3200
#define SM_W2   17600                   // 288
#define SM_T2   17888                   // 32
#define SM_FC1  17920                   // 256
#define SM_WORDS 18176                  // 72704 bytes

// ---------------- main fused network: 8 threads (an "octet") per sample ----------------
__global__ void __launch_bounds__(256, 3) main_kernel(
    const float* __restrict__ x,
    const float* __restrict__ wfc2, const float* __restrict__ wfc3,
    float* __restrict__ out, int B) {

    extern __shared__ unsigned sm[];
    unsigned* s_lut = sm + SM_LUT;
    unsigned* s_w2  = sm + SM_W2;
    int*      s_T2  = (int*)(sm + SM_T2);
    unsigned* s_fc1 = sm + SM_FC1;

    const int tid = threadIdx.x;
    for (int i = tid; i < 12288; i += 256) s_lut[i] = g_lut[i];
    for (int i = tid; i < 288; i += 256) s_w2[i] = g_w2[i];
    for (int i = tid; i < 32; i += 256) s_T2[i] = g_T2[i];
    for (int i = tid; i < 256; i += 256) s_fc1[i] = g_fc1[i];
    __syncthreads();

    const int lane = tid & 31;
    const int base = blockIdx.x * 32;

    // ---- binarize + pack: each warp packs its 4 samples (coalesced loads + ballot) ----
    for (int ss = 0; ss < 4; ++ss) {
        int slot = (tid >> 5) * 4 + ss;
        int samp = base + slot;
        if (samp >= B) break;                       // uniform within warp
        const float* xs = x + (size_t)samp * 1452;
        unsigned* dst = sm + SM_S1 + slot * 100;    // 46-word bitstream staging
        for (int j0 = 0; j0 < 46; j0 += 8) {
            float v[8];
#pragma unroll
            for (int k = 0; k < 8; ++k) {
                int idx = (j0 + k) * 32 + lane;
                v[k] = (idx < 1452) ? xs[idx] : -1.f;
            }
#pragma unroll
            for (int k = 0; k < 8; ++k) {
                unsigned b = __ballot_sync(0xFFFFFFFFu, v[k] >= 0.f);
                if (lane == k && (j0 + k) < 46) dst[j0 + k] = b;
            }
        }
    }
    __syncwarp();

    const int gt = blockIdx.x * 256 + tid;
    const int s = gt >> 3;        // sample
    const int r = gt & 7;         // lane within octet
    if (s >= B) return;           // B multiple of 32 -> whole warps exit together
    const int sl = tid >> 3;      // sample slot in CTA (0..31)

    unsigned* pinw = sm + SM_PIN + sl * 66;
    unsigned* s1   = sm + SM_S1 + sl * 100;

    // re-align bitstream to 22-bit row words: word i covers bits [22i, 22i+22)
    {
        const unsigned* st = s1;
        for (int i = r; i < 66; i += 8) {
            int off = i * 22;
            pinw[i] = __funnelshift_r(st[off >> 5], st[(off >> 5) + 1], off & 31) & 0x3FFFFFu;
        }
    }
    __syncwarp();

    const unsigned* __restrict__ pin = pinw;

    // ---- conv1 via SWAR LUT (uint4 fetches) + threshold + pool -> s1[10][10], bit = oc ----
    for (int py = 0; py < 10; ++py) {
        unsigned rows[12];
#pragma unroll
        for (int c = 0; c < 3; ++c)
#pragma unroll
            for (int k = 0; k < 4; ++k) rows[c * 4 + k] = pin[c * 22 + 2 * py + k];
        // lane owns cells with (py*10+px) % 8 == r  ->  px ≡ (r + 6*py) (mod 8)
        int px0 = (r + 6 * py) & 7;
        for (int px = px0; px < 10; px += 8) {
            unsigned Aw[7];
#pragma unroll
            for (int g = 0; g < 7; ++g) Aw[g] = 0xFFFFFFFFu;
#pragma unroll
            for (int yy = 0; yy < 2; ++yy)
#pragma unroll
                for (int xx = 0; xx < 2; ++xx) {
                    int x0 = 2 * px + xx;
                    unsigned k0 = ((rows[0 + yy] >> x0) & 7u)
                                | (((rows[1 + yy] >> x0) & 7u) << 3)
                                | (((rows[2 + yy] >> x0) & 7u) << 6);
                    unsigned k1 = ((rows[4 + yy] >> x0) & 7u)
                                | (((rows[5 + yy] >> x0) & 7u) << 3)
                                | (((rows[6 + yy] >> x0) & 7u) << 6);
                    unsigned k2 = ((rows[8 + yy] >> x0) & 7u)
                                | (((rows[9 + yy] >> x0) & 7u) << 3)
                                | (((rows[10 + yy] >> x0) & 7u) << 6);
                    const uint4* P0 = (const uint4*)(s_lut + k0 * 8);
                    const uint4* P1 = (const uint4*)(s_lut + (512 + k1) * 8);
                    const uint4* P2 = (const uint4*)(s_lut + (1024 + k2) * 8);
                    uint4 a0 = P0[0], a1 = P0[1];
                    uint4 b0 = P1[0], b1 = P1[1];
                    uint4 c0 = P2[0], c1 = P2[1];
                    Aw[0] &= a0.x + b0.x + c0.x;
                    Aw[1] &= a0.y + b0.y + c0.y;
                    Aw[2] &= a0.z + b0.z + c0.z;
                    Aw[3] &= a0.w + b0.w + c0.w;
                    Aw[4] &= a1.x + b1.x + c1.x;
                    Aw[5] &= a1.y + b1.y + c1.y;
                    Aw[6] &= a1.z + b1.z + c1.z;
                }
            unsigned acc = 0;
#pragma unroll
            for (int g = 0; g < 7; ++g) {
                unsigned xb = (~Aw[g] & 0x20820820u) >> 5;   // keep bits at 0,6,12,18,24
                unsigned y = (xb * 0x108421u) >> 20;          // compress to 5 consecutive bits
                acc |= (y & 31u) << (5 * g);                  // g=6: bits>=32 drop (oc 30,31 ok)
            }
            s1[py * 10 + px] = acc;
        }
    }
    __syncwarp();

    // ---- conv2 (288-term): lane owns pooled row r>>1, 2 cells, all 32 oc ----
    // s2 staged into the (now dead) pin area: pinw[0..15]
    {
        const int pr = r >> 1;            // 0..3
        const int pcb = (r & 1) * 2;      // 0 or 2
        unsigned R[4][6];                 // rows 2pr..2pr+3, cols 2*pcb .. 2*pcb+5
#pragma unroll
        for (int y = 0; y < 4; ++y)
#pragma unroll
            for (int xx = 0; xx < 6; ++xx) R[y][xx] = s1[(2 * pr + y) * 10 + 2 * pcb + xx];
        unsigned acc0 = 0u, acc1 = 0u;
#pragma unroll 2
        for (int oc = 0; oc < 32; ++oc) {
            unsigned w[9];
#pragma unroll
            for (int j = 0; j < 9; ++j) w[j] = s_w2[oc * 9 + j];
            int T = s_T2[oc];
#pragma unroll
            for (int cell = 0; cell < 2; ++cell) {
                const int cb = 2 * cell;
                int c0 = popc9(R[0][cb] ^ w[0], R[0][cb + 1] ^ w[1], R[0][cb + 2] ^ w[2],
                               R[1][cb] ^ w[3], R[1][cb + 1] ^ w[4], R[1][cb + 2] ^ w[5],
                               R[2][cb] ^ w[6], R[2][cb + 1] ^ w[7], R[2][cb + 2] ^ w[8]);
                int c1 = popc9(R[0][cb + 1] ^ w[0], R[0][cb + 2] ^ w[1], R[0][cb + 3] ^ w[2],
                               R[1][cb + 1] ^ w[3], R[1][cb + 2] ^ w[4], R[1][cb + 3] ^ w[5],
                               R[2][cb + 1] ^ w[6], R[2][cb + 2] ^ w[7], R[2][cb + 3] ^ w[8]);
                int c2 = popc9(R[1][cb] ^ w[0], R[1][cb + 1] ^ w[1], R[1][cb + 2] ^ w[2],
                               R[2][cb] ^ w[3], R[2][cb + 1] ^ w[4], R[2][cb + 2] ^ w[5],
                               R[3][cb] ^ w[6], R[3][cb + 1] ^ w[7], R[3][cb + 2] ^ w[8]);
                int c3 = popc9(R[1][cb + 1] ^ w[0], R[1][cb + 2] ^ w[1], R[1][cb + 3] ^ w[2],
                               R[2][cb + 1] ^ w[3], R[2][cb + 2] ^ w[4], R[2][cb + 3] ^ w[5],
                               R[3][cb + 1] ^ w[6], R[3][cb + 2] ^ w[7], R[3][cb + 3] ^ w[8]);
                int m = min(min(c0, c1), min(c2, c3));
                if (cell == 0) acc0 |= (m <= T) ? (1u << oc) : 0u;
                else           acc1 |= (m <= T) ? (1u << oc) : 0u;
            }
        }
        pinw[pr * 4 + pcb]     = acc0;
        pinw[pr * 4 + pcb + 1] = acc1;
    }
    __syncwarp();

    // ---- conv3 (288-term, 64 oc; 8 per lane) + pool -> 64 bits (a0,a1) ----
    unsigned S2[16];
#pragma unroll
    for (int i = 0; i < 16; ++i) S2[i] = pinw[i];

    unsigned p0 = 0u, p1 = 0u;
    const int ocb3 = r * 8;
#pragma unroll 1
    for (int k = 0; k < 8; ++k) {
        int oc = ocb3 + k;
        unsigned w[9];
#pragma unroll
        for (int j = 0; j < 9; ++j) w[j] = __ldg(&g_w3[oc * 9 + j]);
        int T = __ldg(&g_T3[oc]);
        int c0 = popc9(S2[0] ^ w[0], S2[1] ^ w[1], S2[2] ^ w[2],
                       S2[4] ^ w[3], S2[5] ^ w[4], S2[6] ^ w[5],
                       S2[8] ^ w[6], S2[9] ^ w[7], S2[10] ^ w[8]);
        int c1 = popc9(S2[1] ^ w[0], S2[2] ^ w[1], S2[3] ^ w[2],
                       S2[5] ^ w[3], S2[6] ^ w[4], S2[7] ^ w[5],
                       S2[9] ^ w[6], S2[10] ^ w[7], S2[11] ^ w[8]);
        int c2 = popc9(S2[4] ^ w[0], S2[5] ^ w[1], S2[6] ^ w[2],
                       S2[8] ^ w[3], S2[9] ^ w[4], S2[10] ^ w[5],
                       S2[12] ^ w[6], S2[13] ^ w[7], S2[14] ^ w[8]);
        int c3 = popc9(S2[5] ^ w[0], S2[6] ^ w[1], S2[7] ^ w[2],
                       S2[9] ^ w[3], S2[10] ^ w[4], S2[11] ^ w[5],
                       S2[13] ^ w[6], S2[14] ^ w[7], S2[15] ^ w[8]);
        int m = min(min(c0, c1), min(c2, c3));
        unsigned mbit = (m <= T) ? (1u << (oc & 31)) : 0u;
        if (r < 4) p0 |= mbit; else p1 |= mbit;
    }
    unsigned a0 = p0, a1 = p1;
    a0 |= __shfl_xor_sync(0xFFFFFFFFu, a0, 1); a0 |= __shfl_xor_sync(0xFFFFFFFFu, a0, 2);
    a0 |= __shfl_xor_sync(0xFFFFFFFFu, a0, 4);
    a1 |= __shfl_xor_sync(0xFFFFFFFFu, a1, 1); a1 |= __shfl_xor_sync(0xFFFFFFFFu, a1, 2);
    a1 |= __shfl_xor_sync(0xFFFFFFFFu, a1, 4);

    // ---- fc1 (binary 64-dot) + bn4 + hardtanh, fused with the two float heads ----
    float t0 = 0.f, t1 = 0.f, u0 = 0.f, u1 = 0.f, u2 = 0.f, u3 = 0.f;
    const int jb = r * 16;
#pragma unroll 4
    for (int k = 0; k < 16; ++k) {
        int j = jb + k;
        int cnt = __popc(a0 ^ s_fc1[2 * j]) + __popc(a1 ^ s_fc1[2 * j + 1]);
        float sv = (float)(64 - 2 * cnt);
        float h = fminf(1.f, fmaxf(-1.f, fmaf(sv, __ldg(&g_a4[j]), __ldg(&g_c4[j]))));
        t0 = fmaf(h, __ldg(&wfc2[j]), t0);
        t1 = fmaf(h, __ldg(&wfc2[128 + j]), t1);
        u0 = fmaf(h, __ldg(&wfc3[j]), u0);
        u1 = fmaf(h, __ldg(&wfc3[128 + j]), u1);
        u2 = fmaf(h, __ldg(&wfc3[256 + j]), u2);
        u3 = fmaf(h, __ldg(&wfc3[384 + j]), u3);
    }
#pragma unroll
    for (int d = 1; d < 8; d <<= 1) {
        t0 += __shfl_xor_sync(0xFFFFFFFFu, t0, d);
        t1 += __shfl_xor_sync(0xFFFFFFFFu, t1, d);
        u0 += __shfl_xor_sync(0xFFFFFFFFu, u0, d);
        u1 += __shfl_xor_sync(0xFFFFFFFFu, u1, d);
        u2 += __shfl_xor_sync(0xFFFFFFFFu, u2, d);
        u3 += __shfl_xor_sync(0xFFFFFFFFu, u3, d);
    }
    if (r == 0) {
        float z0 = fmaf(t0, g_head[0], g_head[2]);
        float z1 = fmaf(t1, g_head[1], g_head[3]);
        float mx = fmaxf(z0, z1);
        float e0 = expf(z0 - mx), e1 = expf(z1 - mx);
        float is = 1.f / (e0 + e1);
        out[2 * s]     = e0 * is;
        out[2 * s + 1] = e1 * is;
        float* o2 = out + (size_t)2 * B;
        o2[4 * s]     = fmaf(u0, g_head[4], g_head[8]);
        o2[4 * s + 1] = fmaf(u1, g_head[5], g_head[9]);
        o2[4 * s + 2] = fmaf(u2, g_head[6], g_head[10]);
        o2[4 * s + 3] = fmaf(u3, g_head[7], g_head[11]);
    }
}

// ---------------- launch ----------------
extern "C" void kernel_launch(void* const* d_in, const int* in_sizes, int n_in,
                              void* d_out, int out_size) {
    (void)n_in; (void)out_size;
    const float* x    = (const float*)d_in[0];
    const float* w1   = (const float*)d_in[1];
    const float* w2   = (const float*)d_in[2];
    const float* w3   = (const float*)d_in[3];
    const float* wfc1 = (const float*)d_in[4];
    const float* wfc2 = (const float*)d_in[5];
    const float* wfc3 = (const float*)d_in[6];
    const float* bn1  = (const float*)d_in[7];
    const float* bn2  = (const float*)d_in[8];
    const float* bn3  = (const float*)d_in[9];
    const float* bn4  = (const float*)d_in[10];
    const float* bn5  = (const float*)d_in[11];
    const float* bn6  = (const float*)d_in[12];

    int B = in_sizes[0] / 1452;  // 3*22*22
    if (B > MAXB) B = MAXB;

    cudaFuncSetAttribute(main_kernel, cudaFuncAttributeMaxDynamicSharedMemorySize,
                         SM_WORDS * (int)sizeof(unsigned));

    prep_kernel<<<8, 256>>>(w1, w2, w3, wfc1, bn1, bn2, bn3, bn4, bn5, bn6);
    main_kernel<<<(B * 8 + 255) / 256, 256, SM_WORDS * sizeof(unsigned)>>>(
        x, wfc2, wfc3, (float*)d_out, B);
}

// round 9
// speedup vs baseline: 1.1364x; 1.1364x over previous
#include <cuda_runtime.h>
#include <math.h>

#define MAXB 16384

// ---------------- device scratch (no allocations allowed) ----------------
// LUT layout (split arrays, mirrors smem):
//   [0,6144)      A: uint4 per record (words 0-3), record = ch*512+key
//   [6144,9216)   B: uint2 per record (words 4-5)
//   [9216,10752)  C: scalar per record (word 6)
__device__ unsigned g_lut[10752];
__device__ unsigned g_w2r[384];            // [oc*12]: w[0..8], T2, pad, pad
__device__ unsigned g_w3[576];             // [oc*9 + dy*3+dx], bit = input channel
__device__ int      g_T3[64];
__device__ unsigned g_fc1[256];            // [j*2 + half], bit k = sign(w_fc1[j][half*32+k])
__device__ float    g_a4[128], g_c4[128];  // bn4 folded: h = clamp(a*s + c)
__device__ float    g_head[12];            // a5[2], c5[2], a6[4], c6[4]

// ---------------- bn threshold helper ----------------
__device__ __forceinline__ double bn_thresh_t(const float* bn, int C, int c) {
    // bn rows: gamma, beta, mean, var.  sign(bn(s)) >= 0  <=>  s >= m - b*sqrt(v+eps)/g   (g > 0)
    double g = bn[c], b = bn[C + c], m = bn[2 * C + c], v = bn[3 * C + c];
    return m - b * sqrt(v + 1e-5) / g;
}

// ---------------- prep: weight packing + thresholds + conv1 LUT (8 CTAs) ----------------
__global__ void prep_kernel(const float* __restrict__ w1, const float* __restrict__ w2,
                            const float* __restrict__ w3, const float* __restrict__ wfc1,
                            const float* __restrict__ bn1, const float* __restrict__ bn2,
                            const float* __restrict__ bn3, const float* __restrict__ bn4,
                            const float* __restrict__ bn5, const float* __restrict__ bn6) {
    __shared__ unsigned s_wc[96];   // [ch*32+oc]: 9-bit channel slice of w1
    __shared__ int      s_off[32];  // 31 - clamp(T1, -5, 31)

    const int t = blockIdx.x * 256 + threadIdx.x;
    const int nt = 8 * 256;

    if (threadIdx.x < 96) {
        int ch = threadIdx.x / 32, oc = threadIdx.x & 31;
        unsigned w = 0;
        for (int k = 0; k < 9; ++k)
            if (w1[oc * 27 + ch * 9 + k] >= 0.f) w |= 1u << k;
        s_wc[threadIdx.x] = w;
    }
    if (threadIdx.x < 32) {
        int oc = threadIdx.x;
        int T = (int)floor((27.0 - bn_thresh_t(bn1, 32, oc)) * 0.5);  // keep iff cnt <= T
        if (T < -5) T = -5;
        if (T > 31) T = 31;
        s_off[oc] = 31 - T;   // reject iff cnt + off >= 32
    }
    __syncthreads();

    // conv1 LUT: 1536 records of 7 words, split A/B/C
    for (int i = t; i < 1536; i += nt) {
        int ch = i / 512, key = i & 511;
        unsigned wrd[7];
        for (int g = 0; g < 7; ++g) {
            unsigned word = 0;
            for (int j = 0; j < 5; ++j) {
                int oc = 5 * g + j;
                if (oc < 32) {
                    unsigned f = (unsigned)__popc((key ^ s_wc[ch * 32 + oc]) & 0x1FF);
                    if (ch == 2) f += (unsigned)s_off[oc];
                    word |= f << (6 * j);
                }
            }
            wrd[g] = word;
        }
        g_lut[i * 4 + 0] = wrd[0];
        g_lut[i * 4 + 1] = wrd[1];
        g_lut[i * 4 + 2] = wrd[2];
        g_lut[i * 4 + 3] = wrd[3];
        g_lut[6144 + i * 2 + 0] = wrd[4];
        g_lut[6144 + i * 2 + 1] = wrd[5];
        g_lut[9216 + i] = wrd[6];
    }

    // conv2 weight records: 12 words per oc (w0..w8, T2, pad, pad)
    for (int oc = t; oc < 32; oc += nt) {
        for (int p = 0; p < 9; ++p) {
            unsigned w = 0;
            for (int c = 0; c < 32; ++c) if (w2[(oc * 32 + c) * 9 + p] >= 0.f) w |= 1u << c;
            g_w2r[oc * 12 + p] = w;
        }
        g_w2r[oc * 12 + 9]  = (unsigned)(int)floor((288.0 - bn_thresh_t(bn2, 32, oc)) * 0.5);
        g_w2r[oc * 12 + 10] = 0;
        g_w2r[oc * 12 + 11] = 0;
    }
    for (int i = t; i < 576; i += nt) {
        int oc = i / 9, p = i % 9; unsigned w = 0;
        for (int c = 0; c < 32; ++c) if (w3[(oc * 32 + c) * 9 + p] >= 0.f) w |= 1u << c;
        g_w3[i] = w;
    }
    for (int oc = t; oc < 64; oc += nt)
        g_T3[oc] = (int)floor((288.0 - bn_thresh_t(bn3, 64, oc)) * 0.5);
    for (int i = t; i < 256; i += nt) {
        int j = i >> 1, h = i & 1; unsigned w = 0;
        for (int k = 0; k < 32; ++k) if (wfc1[j * 64 + h * 32 + k] >= 0.f) w |= 1u << k;
        g_fc1[i] = w;
    }
    for (int j = t; j < 128; j += nt) {
        float g = bn4[j], b = bn4[128 + j], m = bn4[256 + j], v = bn4[384 + j];
        float inv = g * rsqrtf(v + 1e-5f);
        g_a4[j] = inv; g_c4[j] = b - m * inv;
    }
    if (t < 2) {
        float g = bn5[t], b = bn5[2 + t], m = bn5[4 + t], v = bn5[6 + t];
        float inv = g * rsqrtf(v + 1e-5f);
        g_head[t] = inv; g_head[2 + t] = b - m * inv;
    }
    if (t >= 4 && t < 8) {
        int q = t - 4;
        float g = bn6[q], b = bn6[4 + q], m = bn6[8 + q], v = bn6[12 + q];
        float inv = g * rsqrtf(v + 1e-5f);
        g_head[4 + q] = inv; g_head[8 + q] = b - m * inv;
    }
}

// naive 9-word popcount sum
__device__ __forceinline__ int popc9(unsigned x0, unsigned x1, unsigned x2,
                                     unsigned x3, unsigned x4, unsigned x5,
                                     unsigned x6, unsigned x7, unsigned x8) {
    return __popc(x0) + __popc(x1) + __popc(x2)
         + __popc(x3) + __popc(x4) + __popc(x5)
         + __popc(x6) + __popc(x7) + __popc(x8);
}

// dynamic smem word offsets (128-thread CTA, 16 samples)
#define SM_LUTA 0                       // 6144 words (1536 uint4)
#define SM_LUTB 6144                    // 3072 words (1536 uint2)
#define SM_LUTC 9216                    // 1536 words
#define SM_PIN  10752                   // 16*66 = 1056
#define SM_S1   11808                   // 16*100 = 1600
#define SM_W2   13408                   // 384 (32 recs x 12 words, 16B aligned)
#define SM_FC1  13792                   // 256
#define SM_WORDS 14048                  // 56192 bytes

// ---------------- main fused network: 8 threads (an "octet") per sample ----------------
__global__ void __launch_bounds__(128, 4) main_kernel(
    const float* __restrict__ x,
    const float* __restrict__ wfc2, const float* __restrict__ wfc3,
    float* __restrict__ out, int B) {

    extern __shared__ unsigned sm[];
    unsigned* s_fc1 = sm + SM_FC1;

    const int tid = threadIdx.x;
    for (int i = tid; i < 10752; i += 128) sm[i] = g_lut[i];
    for (int i = tid; i < 384; i += 128) sm[SM_W2 + i] = g_w2r[i];
    for (int i = tid; i < 256; i += 128) s_fc1[i] = g_fc1[i];
    __syncthreads();

    const int lane = tid & 31;
    const int base = blockIdx.x * 16;

    // ---- binarize + pack: each warp packs its 4 samples (coalesced loads + ballot) ----
    for (int ss = 0; ss < 4; ++ss) {
        int slot = (tid >> 5) * 4 + ss;
        int samp = base + slot;
        if (samp >= B) break;                       // uniform within warp
        const float* xs = x + (size_t)samp * 1452;
        unsigned* dst = sm + SM_S1 + slot * 100;    // 46-word bitstream staging
        for (int j0 = 0; j0 < 46; j0 += 8) {
            float v[8];
#pragma unroll
            for (int k = 0; k < 8; ++k) {
                int idx = (j0 + k) * 32 + lane;
                v[k] = (idx < 1452) ? xs[idx] : -1.f;
            }
#pragma unroll
            for (int k = 0; k < 8; ++k) {
                unsigned b = __ballot_sync(0xFFFFFFFFu, v[k] >= 0.f);
                if (lane == k && (j0 + k) < 46) dst[j0 + k] = b;
            }
        }
    }
    __syncwarp();

    const int gt = blockIdx.x * 128 + tid;
    const int s = gt >> 3;        // sample
    const int r = gt & 7;         // lane within octet
    if (s >= B) return;           // B multiple of 16 -> whole warps exit together
    const int sl = tid >> 3;      // sample slot in CTA (0..15)

    unsigned* pinw = sm + SM_PIN + sl * 66;
    unsigned* s1   = sm + SM_S1 + sl * 100;

    // re-align bitstream to 22-bit row words: word i covers bits [22i, 22i+22)
    {
        const unsigned* st = s1;
        for (int i = r; i < 66; i += 8) {
            int off = i * 22;
            pinw[i] = __funnelshift_r(st[off >> 5], st[(off >> 5) + 1], off & 31) & 0x3FFFFFu;
        }
    }
    __syncwarp();

    const unsigned* __restrict__ pin = pinw;
    const uint4* __restrict__ LA = (const uint4*)(sm + SM_LUTA);
    const uint2* __restrict__ LB = (const uint2*)(sm + SM_LUTB);
    const unsigned* __restrict__ LC = sm + SM_LUTC;

    // ---- conv1 via SWAR LUT (A/B/C split fetch) + threshold + pool -> s1[10][10], bit = oc ----
    for (int py = 0; py < 10; ++py) {
        unsigned rows[12];
#pragma unroll
        for (int c = 0; c < 3; ++c)
#pragma unroll
            for (int k = 0; k < 4; ++k) rows[c * 4 + k] = pin[c * 22 + 2 * py + k];
        // lane owns cells with (py*10+px) % 8 == r  ->  px ≡ (r + 6*py) (mod 8)
        int px0 = (r + 6 * py) & 7;
        for (int px = px0; px < 10; px += 8) {
            unsigned Aw[7];
#pragma unroll
            for (int g = 0; g < 7; ++g) Aw[g] = 0xFFFFFFFFu;
#pragma unroll
            for (int yy = 0; yy < 2; ++yy)
#pragma unroll
                for (int xx = 0; xx < 2; ++xx) {
                    int x0 = 2 * px + xx;
                    int K0 = (int)(((rows[0 + yy] >> x0) & 7u)
                                 | (((rows[1 + yy] >> x0) & 7u) << 3)
                                 | (((rows[2 + yy] >> x0) & 7u) << 6));
                    int K1 = 512 + (int)(((rows[4 + yy] >> x0) & 7u)
                                 | (((rows[5 + yy] >> x0) & 7u) << 3)
                                 | (((rows[6 + yy] >> x0) & 7u) << 6));
                    int K2 = 1024 + (int)(((rows[8 + yy] >> x0) & 7u)
                                 | (((rows[9 + yy] >> x0) & 7u) << 3)
                                 | (((rows[10 + yy] >> x0) & 7u) << 6));
                    uint4 a0 = LA[K0], a1 = LA[K1], a2 = LA[K2];
                    uint2 b0 = LB[K0], b1 = LB[K1], b2 = LB[K2];
                    unsigned c0 = LC[K0], c1 = LC[K1], c2 = LC[K2];
                    Aw[0] &= a0.x + a1.x + a2.x;
                    Aw[1] &= a0.y + a1.y + a2.y;
                    Aw[2] &= a0.z + a1.z + a2.z;
                    Aw[3] &= a0.w + a1.w + a2.w;
                    Aw[4] &= b0.x + b1.x + b2.x;
                    Aw[5] &= b0.y + b1.y + b2.y;
                    Aw[6] &= c0 + c1 + c2;
                }
            unsigned acc = 0;
#pragma unroll
            for (int g = 0; g < 7; ++g) {
                unsigned xb = (~Aw[g] & 0x20820820u) >> 5;   // keep bits at 0,6,12,18,24
                unsigned y = (xb * 0x108421u) >> 20;          // compress to 5 consecutive bits
                acc |= (y & 31u) << (5 * g);                  // g=6: bits>=32 drop (oc 30,31 ok)
            }
            s1[py * 10 + px] = acc;
        }
    }
    __syncwarp();

    // ---- conv2 (288-term): lane owns pooled row r>>1, 2 cells, all 32 oc ----
    // s2 staged into the (now dead) pin area: pinw[0..15]
    {
        const int pr = r >> 1;            // 0..3
        const int pcb = (r & 1) * 2;      // 0 or 2
        unsigned R[4][6];                 // rows 2pr..2pr+3, cols 2*pcb .. 2*pcb+5
#pragma unroll
        for (int y = 0; y < 4; ++y)
#pragma unroll
            for (int xx = 0; xx < 6; ++xx) R[y][xx] = s1[(2 * pr + y) * 10 + 2 * pcb + xx];
        unsigned acc0 = 0u, acc1 = 0u;
        const uint4* W = (const uint4*)(sm + SM_W2);
#pragma unroll 2
        for (int oc = 0; oc < 32; ++oc) {
            uint4 wa = W[oc * 3 + 0];
            uint4 wb = W[oc * 3 + 1];
            uint4 wc = W[oc * 3 + 2];
            unsigned w[9] = {wa.x, wa.y, wa.z, wa.w, wb.x, wb.y, wb.z, wb.w, wc.x};
            int T = (int)wc.y;
#pragma unroll
            for (int cell = 0; cell < 2; ++cell) {
                const int cb = 2 * cell;
                int c0 = popc9(R[0][cb] ^ w[0], R[0][cb + 1] ^ w[1], R[0][cb + 2] ^ w[2],
                               R[1][cb] ^ w[3], R[1][cb + 1] ^ w[4], R[1][cb + 2] ^ w[5],
                               R[2][cb] ^ w[6], R[2][cb + 1] ^ w[7], R[2][cb + 2] ^ w[8]);
                int c1 = popc9(R[0][cb + 1] ^ w[0], R[0][cb + 2] ^ w[1], R[0][cb + 3] ^ w[2],
                               R[1][cb + 1] ^ w[3], R[1][cb + 2] ^ w[4], R[1][cb + 3] ^ w[5],
                               R[2][cb + 1] ^ w[6], R[2][cb + 2] ^ w[7], R[2][cb + 3] ^ w[8]);
                int c2 = popc9(R[1][cb] ^ w[0], R[1][cb + 1] ^ w[1], R[1][cb + 2] ^ w[2],
                               R[2][cb] ^ w[3], R[2][cb + 1] ^ w[4], R[2][cb + 2] ^ w[5],
                               R[3][cb] ^ w[6], R[3][cb + 1] ^ w[7], R[3][cb + 2] ^ w[8]);
                int c3 = popc9(R[1][cb + 1] ^ w[0], R[1][cb + 2] ^ w[1], R[1][cb + 3] ^ w[2],
                               R[2][cb + 1] ^ w[3], R[2][cb + 2] ^ w[4], R[2][cb + 3] ^ w[5],
                               R[3][cb + 1] ^ w[6], R[3][cb + 2] ^ w[7], R[3][cb + 3] ^ w[8]);
                int m = min(min(c0, c1), min(c2, c3));
                if (cell == 0) acc0 |= (m <= T) ? (1u << oc) : 0u;
                else           acc1 |= (m <= T) ? (1u << oc) : 0u;
            }
        }
        pinw[pr * 4 + pcb]     = acc0;
        pinw[pr * 4 + pcb + 1] = acc1;
    }
    __syncwarp();

    // ---- conv3 (288-term, 64 oc; 8 per lane) + pool -> 64 bits (a0,a1) ----
    unsigned S2[16];
#pragma unroll
    for (int i = 0; i < 16; ++i) S2[i] = pinw[i];

    unsigned p0 = 0u, p1 = 0u;
    const int ocb3 = r * 8;
#pragma unroll 1
    for (int k = 0; k < 8; ++k) {
        int oc = ocb3 + k;
        unsigned w[9];
#pragma unroll
        for (int j = 0; j < 9; ++j) w[j] = __ldg(&g_w3[oc * 9 + j]);
        int T = __ldg(&g_T3[oc]);
        int c0 = popc9(S2[0] ^ w[0], S2[1] ^ w[1], S2[2] ^ w[2],
                       S2[4] ^ w[3], S2[5] ^ w[4], S2[6] ^ w[5],
                       S2[8] ^ w[6], S2[9] ^ w[7], S2[10] ^ w[8]);
        int c1 = popc9(S2[1] ^ w[0], S2[2] ^ w[1], S2[3] ^ w[2],
                       S2[5] ^ w[3], S2[6] ^ w[4], S2[7] ^ w[5],
                       S2[9] ^ w[6], S2[10] ^ w[7], S2[11] ^ w[8]);
        int c2 = popc9(S2[4] ^ w[0], S2[5] ^ w[1], S2[6] ^ w[2],
                       S2[8] ^ w[3], S2[9] ^ w[4], S2[10] ^ w[5],
                       S2[12] ^ w[6], S2[13] ^ w[7], S2[14] ^ w[8]);
        int c3 = popc9(S2[5] ^ w[0], S2[6] ^ w[1], S2[7] ^ w[2],
                       S2[9] ^ w[3], S2[10] ^ w[4], S2[11] ^ w[5],
                       S2[13] ^ w[6], S2[14] ^ w[7], S2[15] ^ w[8]);
        int m = min(min(c0, c1), min(c2, c3));
        unsigned mbit = (m <= T) ? (1u << (oc & 31)) : 0u;
        if (r < 4) p0 |= mbit; else p1 |= mbit;
    }
    unsigned a0 = p0, a1 = p1;
    a0 |= __shfl_xor_sync(0xFFFFFFFFu, a0, 1); a0 |= __shfl_xor_sync(0xFFFFFFFFu, a0, 2);
    a0 |= __shfl_xor_sync(0xFFFFFFFFu, a0, 4);
    a1 |= __shfl_xor_sync(0xFFFFFFFFu, a1, 1); a1 |= __shfl_xor_sync(0xFFFFFFFFu, a1, 2);
    a1 |= __shfl_xor_sync(0xFFFFFFFFu, a1, 4);

    // ---- fc1 (binary 64-dot) + bn4 + hardtanh, fused with the two float heads ----
    float t0 = 0.f, t1 = 0.f, u0 = 0.f, u1 = 0.f, u2 = 0.f, u3 = 0.f;
    const int jb = r * 16;
#pragma unroll 4
    for (int k = 0; k < 16; ++k) {
        int j = jb + k;
        int cnt = __popc(a0 ^ s_fc1[2 * j]) + __popc(a1 ^ s_fc1[2 * j + 1]);
        float sv = (float)(64 - 2 * cnt);
        float h = fminf(1.f, fmaxf(-1.f, fmaf(sv, __ldg(&g_a4[j]), __ldg(&g_c4[j]))));
        t0 = fmaf(h, __ldg(&wfc2[j]), t0);
        t1 = fmaf(h, __ldg(&wfc2[128 + j]), t1);
        u0 = fmaf(h, __ldg(&wfc3[j]), u0);
        u1 = fmaf(h, __ldg(&wfc3[128 + j]), u1);
        u2 = fmaf(h, __ldg(&wfc3[256 + j]), u2);
        u3 = fmaf(h, __ldg(&wfc3[384 + j]), u3);
    }
#pragma unroll
    for (int d = 1; d < 8; d <<= 1) {
        t0 += __shfl_xor_sync(0xFFFFFFFFu, t0, d);
        t1 += __shfl_xor_sync(0xFFFFFFFFu, t1, d);
        u0 += __shfl_xor_sync(0xFFFFFFFFu, u0, d);
        u1 += __shfl_xor_sync(0xFFFFFFFFu, u1, d);
        u2 += __shfl_xor_sync(0xFFFFFFFFu, u2, d);
        u3 += __shfl_xor_sync(0xFFFFFFFFu, u3, d);
    }
    if (r == 0) {
        float z0 = fmaf(t0, g_head[0], g_head[2]);
        float z1 = fmaf(t1, g_head[1], g_head[3]);
        float mx = fmaxf(z0, z1);
        float e0 = expf(z0 - mx), e1 = expf(z1 - mx);
        float is = 1.f / (e0 + e1);
        out[2 * s]     = e0 * is;
        out[2 * s + 1] = e1 * is;
        float* o2 = out + (size_t)2 * B;
        o2[4 * s]     = fmaf(u0, g_head[4], g_head[8]);
        o2[4 * s + 1] = fmaf(u1, g_head[5], g_head[9]);
        o2[4 * s + 2] = fmaf(u2, g_head[6], g_head[10]);
        o2[4 * s + 3] = fmaf(u3, g_head[7], g_head[11]);
    }
}

// ---------------- launch ----------------
extern "C" void kernel_launch(void* const* d_in, const int* in_sizes, int n_in,
                              void* d_out, int out_size) {
    (void)n_in; (void)out_size;
    const float* x    = (const float*)d_in[0];
    const float* w1   = (const float*)d_in[1];
    const float* w2   = (const float*)d_in[2];
    const float* w3   = (const float*)d_in[3];
    const float* wfc1 = (const float*)d_in[4];
    const float* wfc2 = (const float*)d_in[5];
    const float* wfc3 = (const float*)d_in[6];
    const float* bn1  = (const float*)d_in[7];
    const float* bn2  = (const float*)d_in[8];
    const float* bn3  = (const float*)d_in[9];
    const float* bn4  = (const float*)d_in[10];
    const float* bn5  = (const float*)d_in[11];
    const float* bn6  = (const float*)d_in[12];

    int B = in_sizes[0] / 1452;  // 3*22*22
    if (B > MAXB) B = MAXB;

    cudaFuncSetAttribute(main_kernel, cudaFuncAttributeMaxDynamicSharedMemorySize,
                         SM_WORDS * (int)sizeof(unsigned));

    prep_kernel<<<8, 256>>>(w1, w2, w3, wfc1, bn1, bn2, bn3, bn4, bn5, bn6);
    main_kernel<<<(B * 8 + 127) / 128, 128, SM_WORDS * sizeof(unsigned)>>>(
        x, wfc2, wfc3, (float*)d_out, B);
}

// round 10
// speedup vs baseline: 1.1845x; 1.0423x over previous
#include <cuda_runtime.h>
#include <math.h>

#define MAXB 16384

// ---------------- device scratch (no allocations allowed) ----------------
// LUT layout (split arrays, mirrors smem):
//   [0,6144)      A: uint4 per record (words 0-3), record = ch*512+key
//   [6144,9216)   B: uint2 per record (words 4-5)
//   [9216,10752)  C: scalar per record (word 6)
__device__ unsigned g_lut[10752];
__device__ unsigned g_w2r[384];            // [oc*12]: w[0..8], T2, pad, pad
__device__ unsigned g_w3[576];             // [oc*9 + dy*3+dx], bit = input channel
__device__ int      g_T3[64];
__device__ unsigned g_fc1[256];            // [j*2 + half], bit k = sign(w_fc1[j][half*32+k])
__device__ float    g_a4[128], g_c4[128];  // bn4 folded: h = clamp(a*s + c)
__device__ float    g_head[12];            // a5[2], c5[2], a6[4], c6[4]

// ---------------- bn threshold helper ----------------
__device__ __forceinline__ double bn_thresh_t(const float* bn, int C, int c) {
    // bn rows: gamma, beta, mean, var.  sign(bn(s)) >= 0  <=>  s >= m - b*sqrt(v+eps)/g   (g > 0)
    double g = bn[c], b = bn[C + c], m = bn[2 * C + c], v = bn[3 * C + c];
    return m - b * sqrt(v + 1e-5) / g;
}

// ---------------- prep: weight packing + thresholds + conv1 LUT (8 CTAs) ----------------
__global__ void prep_kernel(const float* __restrict__ w1, const float* __restrict__ w2,
                            const float* __restrict__ w3, const float* __restrict__ wfc1,
                            const float* __restrict__ bn1, const float* __restrict__ bn2,
                            const float* __restrict__ bn3, const float* __restrict__ bn4,
                            const float* __restrict__ bn5, const float* __restrict__ bn6) {
    __shared__ unsigned s_wc[96];   // [ch*32+oc]: 9-bit channel slice of w1
    __shared__ int      s_off[32];  // 31 - clamp(T1, -5, 31)

    const int t = blockIdx.x * 256 + threadIdx.x;
    const int nt = 8 * 256;

    if (threadIdx.x < 96) {
        int ch = threadIdx.x / 32, oc = threadIdx.x & 31;
        unsigned w = 0;
        for (int k = 0; k < 9; ++k)
            if (w1[oc * 27 + ch * 9 + k] >= 0.f) w |= 1u << k;
        s_wc[threadIdx.x] = w;
    }
    if (threadIdx.x < 32) {
        int oc = threadIdx.x;
        int T = (int)floor((27.0 - bn_thresh_t(bn1, 32, oc)) * 0.5);  // keep iff cnt <= T
        if (T < -5) T = -5;
        if (T > 31) T = 31;
        s_off[oc] = 31 - T;   // reject iff cnt + off >= 32
    }
    __syncthreads();

    // conv1 LUT: 1536 records of 7 words, split A/B/C
    for (int i = t; i < 1536; i += nt) {
        int ch = i / 512, key = i & 511;
        unsigned wrd[7];
        for (int g = 0; g < 7; ++g) {
            unsigned word = 0;
            for (int j = 0; j < 5; ++j) {
                int oc = 5 * g + j;
                if (oc < 32) {
                    unsigned f = (unsigned)__popc((key ^ s_wc[ch * 32 + oc]) & 0x1FF);
                    if (ch == 2) f += (unsigned)s_off[oc];
                    word |= f << (6 * j);
                }
            }
            wrd[g] = word;
        }
        g_lut[i * 4 + 0] = wrd[0];
        g_lut[i * 4 + 1] = wrd[1];
        g_lut[i * 4 + 2] = wrd[2];
        g_lut[i * 4 + 3] = wrd[3];
        g_lut[6144 + i * 2 + 0] = wrd[4];
        g_lut[6144 + i * 2 + 1] = wrd[5];
        g_lut[9216 + i] = wrd[6];
    }

    // conv2 weight records: 12 words per oc (w0..w8, T2, pad, pad) — 288-wide packing
    for (int i = t; i < 288; i += nt) {
        int oc = i / 9, p = i % 9; unsigned w = 0;
        for (int c = 0; c < 32; ++c) if (w2[(oc * 32 + c) * 9 + p] >= 0.f) w |= 1u << c;
        g_w2r[oc * 12 + p] = w;
    }
    for (int oc = t; oc < 32; oc += nt) {
        g_w2r[oc * 12 + 9]  = (unsigned)(int)floor((288.0 - bn_thresh_t(bn2, 32, oc)) * 0.5);
        g_w2r[oc * 12 + 10] = 0;
        g_w2r[oc * 12 + 11] = 0;
    }
    for (int i = t; i < 576; i += nt) {
        int oc = i / 9, p = i % 9; unsigned w = 0;
        for (int c = 0; c < 32; ++c) if (w3[(oc * 32 + c) * 9 + p] >= 0.f) w |= 1u << c;
        g_w3[i] = w;
    }
    for (int oc = t; oc < 64; oc += nt)
        g_T3[oc] = (int)floor((288.0 - bn_thresh_t(bn3, 64, oc)) * 0.5);
    for (int i = t; i < 256; i += nt) {
        int j = i >> 1, h = i & 1; unsigned w = 0;
        for (int k = 0; k < 32; ++k) if (wfc1[j * 64 + h * 32 + k] >= 0.f) w |= 1u << k;
        g_fc1[i] = w;
    }
    for (int j = t; j < 128; j += nt) {
        float g = bn4[j], b = bn4[128 + j], m = bn4[256 + j], v = bn4[384 + j];
        float inv = g * rsqrtf(v + 1e-5f);
        g_a4[j] = inv; g_c4[j] = b - m * inv;
    }
    if (t < 2) {
        float g = bn5[t], b = bn5[2 + t], m = bn5[4 + t], v = bn5[6 + t];
        float inv = g * rsqrtf(v + 1e-5f);
        g_head[t] = inv; g_head[2 + t] = b - m * inv;
    }
    if (t >= 4 && t < 8) {
        int q = t - 4;
        float g = bn6[q], b = bn6[4 + q], m = bn6[8 + q], v = bn6[12 + q];
        float inv = g * rsqrtf(v + 1e-5f);
        g_head[4 + q] = inv; g_head[8 + q] = b - m * inv;
    }
}

// naive 9-word popcount sum
__device__ __forceinline__ int popc9(unsigned x0, unsigned x1, unsigned x2,
                                     unsigned x3, unsigned x4, unsigned x5,
                                     unsigned x6, unsigned x7, unsigned x8) {
    return __popc(x0) + __popc(x1) + __popc(x2)
         + __popc(x3) + __popc(x4) + __popc(x5)
         + __popc(x6) + __popc(x7) + __popc(x8);
}

// dynamic smem word offsets (128-thread CTA, 16 samples)
#define SM_LUTA 0                       // 6144 words (1536 uint4)
#define SM_LUTB 6144                    // 3072 words (1536 uint2)
#define SM_LUTC 9216                    // 1536 words
#define SM_PIN  10752                   // 16*66 = 1056
#define SM_S1   11808                   // 16*100 = 1600
#define SM_W2   13408                   // 384 (32 recs x 12 words, 16B aligned)
#define SM_FC1  13792                   // 256
#define SM_WORDS 14048                  // 56192 bytes

// ---------------- main fused network: 8 threads (an "octet") per sample ----------------
__global__ void __launch_bounds__(128, 4) main_kernel(
    const float* __restrict__ x,
    const float* __restrict__ wfc2, const float* __restrict__ wfc3,
    float* __restrict__ out, int B) {

    extern __shared__ unsigned sm[];
    unsigned* s_fc1 = sm + SM_FC1;

    const int tid = threadIdx.x;
    for (int i = tid; i < 10752; i += 128) sm[i] = g_lut[i];
    for (int i = tid; i < 384; i += 128) sm[SM_W2 + i] = g_w2r[i];
    for (int i = tid; i < 256; i += 128) s_fc1[i] = g_fc1[i];
    __syncthreads();

    const int lane = tid & 31;
    const int base = blockIdx.x * 16;

    // ---- binarize + pack: each warp packs its 4 samples (coalesced loads + ballot) ----
    for (int ss = 0; ss < 4; ++ss) {
        int slot = (tid >> 5) * 4 + ss;
        int samp = base + slot;
        if (samp >= B) break;                       // uniform within warp
        const float* xs = x + (size_t)samp * 1452;
        unsigned* dst = sm + SM_S1 + slot * 100;    // 46-word bitstream staging
        for (int j0 = 0; j0 < 46; j0 += 8) {
            float v[8];
#pragma unroll
            for (int k = 0; k < 8; ++k) {
                int idx = (j0 + k) * 32 + lane;
                v[k] = (idx < 1452) ? xs[idx] : -1.f;
            }
#pragma unroll
            for (int k = 0; k < 8; ++k) {
                unsigned b = __ballot_sync(0xFFFFFFFFu, v[k] >= 0.f);
                if (lane == k && (j0 + k) < 46) dst[j0 + k] = b;
            }
        }
    }
    __syncwarp();

    const int gt = blockIdx.x * 128 + tid;
    const int s = gt >> 3;        // sample
    const int r = gt & 7;         // lane within octet
    if (s >= B) return;           // B multiple of 16 -> whole warps exit together
    const int sl = tid >> 3;      // sample slot in CTA (0..15)

    unsigned* pinw = sm + SM_PIN + sl * 66;
    unsigned* s1   = sm + SM_S1 + sl * 100;

    // re-align bitstream to 22-bit row words: word i covers bits [22i, 22i+22)
    {
        const unsigned* st = s1;
        for (int i = r; i < 66; i += 8) {
            int off = i * 22;
            pinw[i] = __funnelshift_r(st[off >> 5], st[(off >> 5) + 1], off & 31) & 0x3FFFFFu;
        }
    }
    __syncwarp();

    const unsigned* __restrict__ pin = pinw;
    const uint4* __restrict__ LA = (const uint4*)(sm + SM_LUTA);
    const uint2* __restrict__ LB = (const uint2*)(sm + SM_LUTB);
    const unsigned* __restrict__ LC = sm + SM_LUTC;

    // ---- conv1 via SWAR LUT (A/B/C split fetch) + threshold + pool -> s1[10][10], bit = oc ----
    for (int py = 0; py < 10; ++py) {
        unsigned rows[12];
#pragma unroll
        for (int c = 0; c < 3; ++c)
#pragma unroll
            for (int k = 0; k < 4; ++k) rows[c * 4 + k] = pin[c * 22 + 2 * py + k];
        // lane owns cells with (py*10+px) % 8 == r  ->  px ≡ (r + 6*py) (mod 8)
        int px0 = (r + 6 * py) & 7;
        for (int px = px0; px < 10; px += 8) {
            unsigned Aw[7];
#pragma unroll
            for (int g = 0; g < 7; ++g) Aw[g] = 0xFFFFFFFFu;
#pragma unroll
            for (int yy = 0; yy < 2; ++yy)
#pragma unroll
                for (int xx = 0; xx < 2; ++xx) {
                    int x0 = 2 * px + xx;
                    int K0 = (int)(((rows[0 + yy] >> x0) & 7u)
                                 | (((rows[1 + yy] >> x0) & 7u) << 3)
                                 | (((rows[2 + yy] >> x0) & 7u) << 6));
                    int K1 = 512 + (int)(((rows[4 + yy] >> x0) & 7u)
                                 | (((rows[5 + yy] >> x0) & 7u) << 3)
                                 | (((rows[6 + yy] >> x0) & 7u) << 6));
                    int K2 = 1024 + (int)(((rows[8 + yy] >> x0) & 7u)
                                 | (((rows[9 + yy] >> x0) & 7u) << 3)
                                 | (((rows[10 + yy] >> x0) & 7u) << 6));
                    uint4 a0 = LA[K0], a1 = LA[K1], a2 = LA[K2];
                    uint2 b0 = LB[K0], b1 = LB[K1], b2 = LB[K2];
                    unsigned c0 = LC[K0], c1 = LC[K1], c2 = LC[K2];
                    Aw[0] &= a0.x + a1.x + a2.x;
                    Aw[1] &= a0.y + a1.y + a2.y;
                    Aw[2] &= a0.z + a1.z + a2.z;
                    Aw[3] &= a0.w + a1.w + a2.w;
                    Aw[4] &= b0.x + b1.x + b2.x;
                    Aw[5] &= b0.y + b1.y + b2.y;
                    Aw[6] &= c0 + c1 + c2;
                }
            unsigned acc = 0;
#pragma unroll
            for (int g = 0; g < 7; ++g) {
                unsigned xb = (~Aw[g] & 0x20820820u) >> 5;   // keep bits at 0,6,12,18,24
                unsigned y = (xb * 0x108421u) >> 20;          // compress to 5 consecutive bits
                acc |= (y & 31u) << (5 * g);                  // g=6: bits>=32 drop (oc 30,31 ok)
            }
            s1[py * 10 + px] = acc;
        }
    }
    __syncwarp();

    // ---- conv2 (288-term): lane owns pooled row r>>1, 2 cells, all 32 oc ----
    // s2 staged into the (now dead) pin area: pinw[0..15]
    {
        const int pr = r >> 1;            // 0..3
        const int pcb = (r & 1) * 2;      // 0 or 2
        unsigned R[4][6];                 // rows 2pr..2pr+3, cols 2*pcb .. 2*pcb+5
#pragma unroll
        for (int y = 0; y < 4; ++y)
#pragma unroll
            for (int xx = 0; xx < 6; ++xx) R[y][xx] = s1[(2 * pr + y) * 10 + 2 * pcb + xx];
        unsigned acc0 = 0u, acc1 = 0u;
        const uint4* W = (const uint4*)(sm + SM_W2);
#pragma unroll 2
        for (int oc = 0; oc < 32; ++oc) {
            uint4 wa = W[oc * 3 + 0];
            uint4 wb = W[oc * 3 + 1];
            uint4 wc = W[oc * 3 + 2];
            unsigned w[9] = {wa.x, wa.y, wa.z, wa.w, wb.x, wb.y, wb.z, wb.w, wc.x};
            int T = (int)wc.y;
#pragma unroll
            for (int cell = 0; cell < 2; ++cell) {
                const int cb = 2 * cell;
                int c0 = popc9(R[0][cb] ^ w[0], R[0][cb + 1] ^ w[1], R[0][cb + 2] ^ w[2],
                               R[1][cb] ^ w[3], R[1][cb + 1] ^ w[4], R[1][cb + 2] ^ w[5],
                               R[2][cb] ^ w[6], R[2][cb + 1] ^ w[7], R[2][cb + 2] ^ w[8]);
                int c1 = popc9(R[0][cb + 1] ^ w[0], R[0][cb + 2] ^ w[1], R[0][cb + 3] ^ w[2],
                               R[1][cb + 1] ^ w[3], R[1][cb + 2] ^ w[4], R[1][cb + 3] ^ w[5],
                               R[2][cb + 1] ^ w[6], R[2][cb + 2] ^ w[7], R[2][cb + 3] ^ w[8]);
                int c2 = popc9(R[1][cb] ^ w[0], R[1][cb + 1] ^ w[1], R[1][cb + 2] ^ w[2],
                               R[2][cb] ^ w[3], R[2][cb + 1] ^ w[4], R[2][cb + 2] ^ w[5],
                               R[3][cb] ^ w[6], R[3][cb + 1] ^ w[7], R[3][cb + 2] ^ w[8]);
                int c3 = popc9(R[1][cb + 1] ^ w[0], R[1][cb + 2] ^ w[1], R[1][cb + 3] ^ w[2],
                               R[2][cb + 1] ^ w[3], R[2][cb + 2] ^ w[4], R[2][cb + 3] ^ w[5],
                               R[3][cb + 1] ^ w[6], R[3][cb + 2] ^ w[7], R[3][cb + 3] ^ w[8]);
                int m = min(min(c0, c1), min(c2, c3));
                if (cell == 0) acc0 |= (m <= T) ? (1u << oc) : 0u;
                else           acc1 |= (m <= T) ? (1u << oc) : 0u;
            }
        }
        pinw[pr * 4 + pcb]     = acc0;
        pinw[pr * 4 + pcb + 1] = acc1;
    }
    __syncwarp();

    // ---- conv3 (288-term, 64 oc; 8 per lane) + pool -> 64 bits (a0,a1) ----
    unsigned S2[16];
#pragma unroll
    for (int i = 0; i < 16; ++i) S2[i] = pinw[i];

    unsigned p0 = 0u, p1 = 0u;
    const int ocb3 = r * 8;
#pragma unroll 1
    for (int k = 0; k < 8; ++k) {
        int oc = ocb3 + k;
        unsigned w[9];
#pragma unroll
        for (int j = 0; j < 9; ++j) w[j] = __ldg(&g_w3[oc * 9 + j]);
        int T = __ldg(&g_T3[oc]);
        int c0 = popc9(S2[0] ^ w[0], S2[1] ^ w[1], S2[2] ^ w[2],
                       S2[4] ^ w[3], S2[5] ^ w[4], S2[6] ^ w[5],
                       S2[8] ^ w[6], S2[9] ^ w[7], S2[10] ^ w[8]);
        int c1 = popc9(S2[1] ^ w[0], S2[2] ^ w[1], S2[3] ^ w[2],
                       S2[5] ^ w[3], S2[6] ^ w[4], S2[7] ^ w[5],
                       S2[9] ^ w[6], S2[10] ^ w[7], S2[11] ^ w[8]);
        int c2 = popc9(S2[4] ^ w[0], S2[5] ^ w[1], S2[6] ^ w[2],
                       S2[8] ^ w[3], S2[9] ^ w[4], S2[10] ^ w[5],
                       S2[12] ^ w[6], S2[13] ^ w[7], S2[14] ^ w[8]);
        int c3 = popc9(S2[5] ^ w[0], S2[6] ^ w[1], S2[7] ^ w[2],
                       S2[9] ^ w[3], S2[10] ^ w[4], S2[11] ^ w[5],
                       S2[13] ^ w[6], S2[14] ^ w[7], S2[15] ^ w[8]);
        int m = min(min(c0, c1), min(c2, c3));
        unsigned mbit = (m <= T) ? (1u << (oc & 31)) : 0u;
        if (r < 4) p0 |= mbit; else p1 |= mbit;
    }
    unsigned a0 = p0, a1 = p1;
    a0 |= __shfl_xor_sync(0xFFFFFFFFu, a0, 1); a0 |= __shfl_xor_sync(0xFFFFFFFFu, a0, 2);
    a0 |= __shfl_xor_sync(0xFFFFFFFFu, a0, 4);
    a1 |= __shfl_xor_sync(0xFFFFFFFFu, a1, 1); a1 |= __shfl_xor_sync(0xFFFFFFFFu, a1, 2);
    a1 |= __shfl_xor_sync(0xFFFFFFFFu, a1, 4);

    // ---- fc1 (binary 64-dot) + bn4 + hardtanh, fused with the two float heads ----
    // Vectorized: float4 loads for a4/c4/wfc2/wfc3 (jb is 16-float = 64B aligned), uint2 for fc1 words.
    float t0 = 0.f, t1 = 0.f, u0 = 0.f, u1 = 0.f, u2 = 0.f, u3 = 0.f;
    const int jb = r * 16;
    const float4* A4v = (const float4*)(g_a4 + jb);
    const float4* C4v = (const float4*)(g_c4 + jb);
    const float4* F2a = (const float4*)(wfc2 + jb);
    const float4* F2b = (const float4*)(wfc2 + 128 + jb);
    const float4* F3a = (const float4*)(wfc3 + jb);
    const float4* F3b = (const float4*)(wfc3 + 128 + jb);
    const float4* F3c = (const float4*)(wfc3 + 256 + jb);
    const float4* F3d = (const float4*)(wfc3 + 384 + jb);
    const uint2* FCW = (const uint2*)s_fc1;

#pragma unroll
    for (int q = 0; q < 4; ++q) {
        float4 a4v = __ldg(&A4v[q]);
        float4 c4v = __ldg(&C4v[q]);
        float4 f2a = __ldg(&F2a[q]);
        float4 f2b = __ldg(&F2b[q]);
        float4 f3a = __ldg(&F3a[q]);
        float4 f3b = __ldg(&F3b[q]);
        float4 f3c = __ldg(&F3c[q]);
        float4 f3d = __ldg(&F3d[q]);
#define FC1_STEP(comp, kk) do {                                             \
        uint2 fw = FCW[jb + 4 * q + (kk)];                                  \
        int cnt = __popc(a0 ^ fw.x) + __popc(a1 ^ fw.y);                    \
        float sv = (float)(64 - 2 * cnt);                                   \
        float h = fminf(1.f, fmaxf(-1.f, fmaf(sv, a4v.comp, c4v.comp)));    \
        t0 = fmaf(h, f2a.comp, t0);  t1 = fmaf(h, f2b.comp, t1);            \
        u0 = fmaf(h, f3a.comp, u0);  u1 = fmaf(h, f3b.comp, u1);            \
        u2 = fmaf(h, f3c.comp, u2);  u3 = fmaf(h, f3d.comp, u3); } while (0)
        FC1_STEP(x, 0);
        FC1_STEP(y, 1);
        FC1_STEP(z, 2);
        FC1_STEP(w, 3);
#undef FC1_STEP
    }
#pragma unroll
    for (int d = 1; d < 8; d <<= 1) {
        t0 += __shfl_xor_sync(0xFFFFFFFFu, t0, d);
        t1 += __shfl_xor_sync(0xFFFFFFFFu, t1, d);
        u0 += __shfl_xor_sync(0xFFFFFFFFu, u0, d);
        u1 += __shfl_xor_sync(0xFFFFFFFFu, u1, d);
        u2 += __shfl_xor_sync(0xFFFFFFFFu, u2, d);
        u3 += __shfl_xor_sync(0xFFFFFFFFu, u3, d);
    }
    if (r == 0) {
        float z0 = fmaf(t0, g_head[0], g_head[2]);
        float z1 = fmaf(t1, g_head[1], g_head[3]);
        float mx = fmaxf(z0, z1);
        float e0 = expf(z0 - mx), e1 = expf(z1 - mx);
        float is = 1.f / (e0 + e1);
        out[2 * s]     = e0 * is;
        out[2 * s + 1] = e1 * is;
        float* o2 = out + (size_t)2 * B;
        o2[4 * s]     = fmaf(u0, g_head[4], g_head[8]);
        o2[4 * s + 1] = fmaf(u1, g_head[5], g_head[9]);
        o2[4 * s + 2] = fmaf(u2, g_head[6], g_head[10]);
        o2[4 * s + 3] = fmaf(u3, g_head[7], g_head[11]);
    }
}

// ---------------- launch ----------------
extern "C" void kernel_launch(void* const* d_in, const int* in_sizes, int n_in,
                              void* d_out, int out_size) {
    (void)n_in; (void)out_size;
    const float* x    = (const float*)d_in[0];
    const float* w1   = (const float*)d_in[1];
    const float* w2   = (const float*)d_in[2];
    const float* w3   = (const float*)d_in[3];
    const float* wfc1 = (const float*)d_in[4];
    const float* wfc2 = (const float*)d_in[5];
    const float* wfc3 = (const float*)d_in[6];
    const float* bn1  = (const float*)d_in[7];
    const float* bn2  = (const float*)d_in[8];
    const float* bn3  = (const float*)d_in[9];
    const float* bn4  = (const float*)d_in[10];
    const float* bn5  = (const float*)d_in[11];
    const float* bn6  = (const float*)d_in[12];

    int B = in_sizes[0] / 1452;  // 3*22*22
    if (B > MAXB) B = MAXB;

    cudaFuncSetAttribute(main_kernel, cudaFuncAttributeMaxDynamicSharedMemorySize,
                         SM_WORDS * (int)sizeof(unsigned));

    prep_kernel<<<8, 256>>>(w1, w2, w3, wfc1, bn1, bn2, bn3, bn4, bn5, bn6);
    main_kernel<<<(B * 8 + 127) / 128, 128, SM_WORDS * sizeof(unsigned)>>>(
        x, wfc2, wfc3, (float*)d_out, B);
}

// round 11
// speedup vs baseline: 1.3317x; 1.1243x over previous
#include <cuda_runtime.h>
#include <math.h>

#define MAXB 16384

// ---------------- device scratch (no allocations allowed) ----------------
// LUT: A[1536 records]xuint4 (slots oc0..19) then B[1536]xuint2 (slots oc20..29)
__device__ __align__(16) unsigned g_lut[9216];
__device__ __align__(16) unsigned g_w2r[384];   // [oc*12]: w[0..8], T2, pad, pad
__device__ unsigned g_w1d[6];                   // ch words for oc30 (0..2), oc31 (3..5)
__device__ int      g_T1d[2];                   // T1 for oc30, oc31
__device__ unsigned g_w3[576];                  // [oc*9 + dy*3+dx], bit = input channel
__device__ int      g_T3[64];
__device__ __align__(16) unsigned g_fc1[256];   // [j*2 + half]
__device__ __align__(16) float g_a4[128];
__device__ __align__(16) float g_c4[128];
__device__ float g_head[12];

// ---------------- bn threshold helper ----------------
__device__ __forceinline__ double bn_thresh_t(const float* bn, int C, int c) {
    double g = bn[c], b = bn[C + c], m = bn[2 * C + c], v = bn[3 * C + c];
    return m - b * sqrt(v + 1e-5) / g;
}

// ---------------- prep: weight packing + thresholds + conv1 LUT (8 CTAs) ----------------
__global__ void prep_kernel(const float* __restrict__ w1, const float* __restrict__ w2,
                            const float* __restrict__ w3, const float* __restrict__ wfc1,
                            const float* __restrict__ bn1, const float* __restrict__ bn2,
                            const float* __restrict__ bn3, const float* __restrict__ bn4,
                            const float* __restrict__ bn5, const float* __restrict__ bn6) {
    __shared__ unsigned s_wc[96];   // [ch*32+oc]: 9-bit channel slice of w1
    __shared__ int      s_off[32];  // 31 - clamp(T1, -5, 31)

    const int t = blockIdx.x * 256 + threadIdx.x;
    const int nt = 8 * 256;

    if (threadIdx.x < 96) {
        int ch = threadIdx.x / 32, oc = threadIdx.x & 31;
        unsigned w = 0;
        for (int k = 0; k < 9; ++k)
            if (w1[oc * 27 + ch * 9 + k] >= 0.f) w |= 1u << k;
        s_wc[threadIdx.x] = w;
    }
    if (threadIdx.x < 32) {
        int oc = threadIdx.x;
        int T = (int)floor((27.0 - bn_thresh_t(bn1, 32, oc)) * 0.5);
        if (T < -5) T = -5;
        if (T > 31) T = 31;
        s_off[oc] = 31 - T;   // reject iff cnt + off >= 32
    }
    __syncthreads();

    // conv1 LUT: 1536 records, 6 words each (A: 4, B: 2) covering oc 0..29
    for (int i = t; i < 1536; i += nt) {
        int ch = i / 512, key = i & 511;
        unsigned wrd[6];
        for (int g = 0; g < 6; ++g) {
            unsigned word = 0;
            for (int j = 0; j < 5; ++j) {
                int oc = 5 * g + j;
                unsigned f = (unsigned)__popc((key ^ s_wc[ch * 32 + oc]) & 0x1FF);
                if (ch == 2) f += (unsigned)s_off[oc];
                word |= f << (6 * j);
            }
            wrd[g] = word;
        }
        g_lut[i * 4 + 0] = wrd[0];
        g_lut[i * 4 + 1] = wrd[1];
        g_lut[i * 4 + 2] = wrd[2];
        g_lut[i * 4 + 3] = wrd[3];
        g_lut[6144 + i * 2 + 0] = wrd[4];
        g_lut[6144 + i * 2 + 1] = wrd[5];
    }
    // direct weights/thresholds for oc 30, 31
    if (t < 6) g_w1d[t] = s_wc[(t % 3) * 32 + 30 + (t / 3)];
    if (t >= 8 && t < 10) {
        int q = t - 8;
        g_T1d[q] = (int)floor((27.0 - bn_thresh_t(bn1, 32, 30 + q)) * 0.5);
    }

    // conv2 weight records: 12 words per oc (w0..w8, T2, pad, pad) — 288-wide packing
    for (int i = t; i < 288; i += nt) {
        int oc = i / 9, p = i % 9; unsigned w = 0;
        for (int c = 0; c < 32; ++c) if (w2[(oc * 32 + c) * 9 + p] >= 0.f) w |= 1u << c;
        g_w2r[oc * 12 + p] = w;
    }
    for (int oc = t; oc < 32; oc += nt) {
        g_w2r[oc * 12 + 9]  = (unsigned)(int)floor((288.0 - bn_thresh_t(bn2, 32, oc)) * 0.5);
        g_w2r[oc * 12 + 10] = 0;
        g_w2r[oc * 12 + 11] = 0;
    }
    for (int i = t; i < 576; i += nt) {
        int oc = i / 9, p = i % 9; unsigned w = 0;
        for (int c = 0; c < 32; ++c) if (w3[(oc * 32 + c) * 9 + p] >= 0.f) w |= 1u << c;
        g_w3[i] = w;
    }
    for (int oc = t; oc < 64; oc += nt)
        g_T3[oc] = (int)floor((288.0 - bn_thresh_t(bn3, 64, oc)) * 0.5);
    for (int i = t; i < 256; i += nt) {
        int j = i >> 1, h = i & 1; unsigned w = 0;
        for (int k = 0; k < 32; ++k) if (wfc1[j * 64 + h * 32 + k] >= 0.f) w |= 1u << k;
        g_fc1[i] = w;
    }
    for (int j = t; j < 128; j += nt) {
        float g = bn4[j], b = bn4[128 + j], m = bn4[256 + j], v = bn4[384 + j];
        float inv = g * rsqrtf(v + 1e-5f);
        g_a4[j] = inv; g_c4[j] = b - m * inv;
    }
    if (t < 2) {
        float g = bn5[t], b = bn5[2 + t], m = bn5[4 + t], v = bn5[6 + t];
        float inv = g * rsqrtf(v + 1e-5f);
        g_head[t] = inv; g_head[2 + t] = b - m * inv;
    }
    if (t >= 4 && t < 8) {
        int q = t - 4;
        float g = bn6[q], b = bn6[4 + q], m = bn6[8 + q], v = bn6[12 + q];
        float inv = g * rsqrtf(v + 1e-5f);
        g_head[4 + q] = inv; g_head[8 + q] = b - m * inv;
    }
}

// naive 9-word popcount sum
__device__ __forceinline__ int popc9(unsigned x0, unsigned x1, unsigned x2,
                                     unsigned x3, unsigned x4, unsigned x5,
                                     unsigned x6, unsigned x7, unsigned x8) {
    return __popc(x0) + __popc(x1) + __popc(x2)
         + __popc(x3) + __popc(x4) + __popc(x5)
         + __popc(x6) + __popc(x7) + __popc(x8);
}

// dynamic smem word offsets (128-thread CTA, 8 samples, 16 lanes/sample)
#define SM_LUTA 0                       // 6144 words (1536 uint4)
#define SM_LUTB 6144                    // 3072 words (1536 uint2)
#define SM_PIN  9216                    // 8*66 = 528
#define SM_S1   9744                    // 8*100 = 800
#define SM_W2   10544                   // 384 (32 recs x 12 words)
#define SM_FC1  10928                   // 256
#define SM_WORDS 11184                  // 44736 bytes

// ---------------- main fused network: 16 threads per sample ----------------
__global__ void __launch_bounds__(128, 5) main_kernel(
    const float* __restrict__ x,
    const float* __restrict__ wfc2, const float* __restrict__ wfc3,
    float* __restrict__ out, int B) {

    extern __shared__ unsigned sm[];
    unsigned* s_fc1 = sm + SM_FC1;

    const int tid = threadIdx.x;
    {   // vectorized fills
        const uint4* srcL = (const uint4*)g_lut;
        uint4* dstL = (uint4*)sm;
        for (int i = tid; i < 2304; i += 128) dstL[i] = srcL[i];
        const uint4* srcW = (const uint4*)g_w2r;
        uint4* dstW = (uint4*)(sm + SM_W2);
        for (int i = tid; i < 96; i += 128) dstW[i] = srcW[i];
        const uint4* srcF = (const uint4*)g_fc1;
        uint4* dstF = (uint4*)(sm + SM_FC1);
        for (int i = tid; i < 64; i += 128) dstF[i] = srcF[i];
    }
    __syncthreads();

    const int lane = tid & 31;
    const int base = blockIdx.x * 8;

    // ---- binarize + pack: each warp packs its 2 samples (coalesced loads + ballot) ----
    for (int ss = 0; ss < 2; ++ss) {
        int slot = (tid >> 5) * 2 + ss;
        int samp = base + slot;
        if (samp >= B) break;                       // uniform within warp
        const float* xs = x + (size_t)samp * 1452;
        unsigned* dst = sm + SM_S1 + slot * 100;    // 46-word bitstream staging
        for (int j0 = 0; j0 < 46; j0 += 8) {
            float v[8];
#pragma unroll
            for (int k = 0; k < 8; ++k) {
                int idx = (j0 + k) * 32 + lane;
                v[k] = (idx < 1452) ? xs[idx] : -1.f;
            }
#pragma unroll
            for (int k = 0; k < 8; ++k) {
                unsigned b = __ballot_sync(0xFFFFFFFFu, v[k] >= 0.f);
                if (lane == k && (j0 + k) < 46) dst[j0 + k] = b;
            }
        }
    }
    __syncwarp();

    const int gt = blockIdx.x * 128 + tid;
    const int s = gt >> 4;        // sample
    const int r = gt & 15;        // lane within 16-group
    if (s >= B) return;           // B multiple of 8 -> whole warps exit together
    const int sl = tid >> 4;      // sample slot in CTA (0..7)

    unsigned* pinw = sm + SM_PIN + sl * 66;
    unsigned* s1   = sm + SM_S1 + sl * 100;

    // re-align bitstream to 22-bit row words
    {
        const unsigned* st = s1;
        for (int i = r; i < 66; i += 16) {
            int off = i * 22;
            pinw[i] = __funnelshift_r(st[off >> 5], st[(off >> 5) + 1], off & 31) & 0x3FFFFFu;
        }
    }
    __syncwarp();

    const unsigned* __restrict__ pin = pinw;
    const uint4* __restrict__ LA = (const uint4*)(sm + SM_LUTA);
    const uint2* __restrict__ LB = (const uint2*)(sm + SM_LUTB);

    // direct oc30/31 weights + thresholds (uniform broadcast loads)
    unsigned wd0 = __ldg(&g_w1d[0]), wd1 = __ldg(&g_w1d[1]), wd2 = __ldg(&g_w1d[2]);
    unsigned wd3 = __ldg(&g_w1d[3]), wd4 = __ldg(&g_w1d[4]), wd5 = __ldg(&g_w1d[5]);
    int T30 = __ldg(&g_T1d[0]), T31 = __ldg(&g_T1d[1]);

    // ---- conv1: LUT (oc 0..29) + direct popc (oc 30,31) + pool -> s1[10][10] ----
    for (int py = 0; py < 10; ++py) {
        // lane owns cell (py,px) iff (py*10+px) % 16 == r  ->  px = (r + 6*py) & 15, if <10
        int px = (r + 6 * py) & 15;
        if (px >= 10) continue;
        unsigned rows[12];
#pragma unroll
        for (int c = 0; c < 3; ++c)
#pragma unroll
            for (int k = 0; k < 4; ++k) rows[c * 4 + k] = pin[c * 22 + 2 * py + k];

        unsigned Aw[6];
#pragma unroll
        for (int g = 0; g < 6; ++g) Aw[g] = 0xFFFFFFFFu;
        int m30 = 99, m31 = 99;
#pragma unroll
        for (int yy = 0; yy < 2; ++yy)
#pragma unroll
            for (int xx = 0; xx < 2; ++xx) {
                int x0 = 2 * px + xx;
                int k0 = (int)(((rows[0 + yy] >> x0) & 7u)
                             | (((rows[1 + yy] >> x0) & 7u) << 3)
                             | (((rows[2 + yy] >> x0) & 7u) << 6));
                int k1 = (int)(((rows[4 + yy] >> x0) & 7u)
                             | (((rows[5 + yy] >> x0) & 7u) << 3)
                             | (((rows[6 + yy] >> x0) & 7u) << 6));
                int k2 = (int)(((rows[8 + yy] >> x0) & 7u)
                             | (((rows[9 + yy] >> x0) & 7u) << 3)
                             | (((rows[10 + yy] >> x0) & 7u) << 6));
                uint4 a0 = LA[k0], a1 = LA[512 + k1], a2 = LA[1024 + k2];
                uint2 b0 = LB[k0], b1 = LB[512 + k1], b2 = LB[1024 + k2];
                Aw[0] &= a0.x + a1.x + a2.x;
                Aw[1] &= a0.y + a1.y + a2.y;
                Aw[2] &= a0.z + a1.z + a2.z;
                Aw[3] &= a0.w + a1.w + a2.w;
                Aw[4] &= b0.x + b1.x + b2.x;
                Aw[5] &= b0.y + b1.y + b2.y;
                int c30 = __popc((unsigned)k0 ^ wd0) + __popc((unsigned)k1 ^ wd1)
                        + __popc((unsigned)k2 ^ wd2);
                int c31 = __popc((unsigned)k0 ^ wd3) + __popc((unsigned)k1 ^ wd4)
                        + __popc((unsigned)k2 ^ wd5);
                m30 = min(m30, c30);
                m31 = min(m31, c31);
            }
        unsigned acc = 0;
#pragma unroll
        for (int g = 0; g < 6; ++g) {
            unsigned xb = (~Aw[g] & 0x20820820u) >> 5;   // keep bits at 0,6,12,18,24
            unsigned y = (xb * 0x108421u) >> 20;          // compress to 5 bits
            acc |= (y & 31u) << (5 * g);                  // oc 0..29
        }
        acc |= (m30 <= T30) ? (1u << 30) : 0u;
        acc |= (m31 <= T31) ? (1u << 31) : 0u;
        s1[py * 10 + px] = acc;
    }
    __syncwarp();

    // ---- conv2 (288-term): lane owns exactly 1 pooled cell (pr=r>>2, pc=r&3), all 32 oc ----
    {
        const int pr = r >> 2;
        const int pc = r & 3;
        unsigned R[4][4];                 // rows 2pr..2pr+3, cols 2pc..2pc+3
#pragma unroll
        for (int y = 0; y < 4; ++y)
#pragma unroll
            for (int xx = 0; xx < 4; ++xx) R[y][xx] = s1[(2 * pr + y) * 10 + 2 * pc + xx];
        unsigned acc = 0u;
        const uint4* W = (const uint4*)(sm + SM_W2);
#pragma unroll 2
        for (int oc = 0; oc < 32; ++oc) {
            uint4 wa = W[oc * 3 + 0];
            uint4 wb = W[oc * 3 + 1];
            uint4 wc = W[oc * 3 + 2];
            unsigned w[9] = {wa.x, wa.y, wa.z, wa.w, wb.x, wb.y, wb.z, wb.w, wc.x};
            int T = (int)wc.y;
            int c0 = popc9(R[0][0] ^ w[0], R[0][1] ^ w[1], R[0][2] ^ w[2],
                           R[1][0] ^ w[3], R[1][1] ^ w[4], R[1][2] ^ w[5],
                           R[2][0] ^ w[6], R[2][1] ^ w[7], R[2][2] ^ w[8]);
            int c1 = popc9(R[0][1] ^ w[0], R[0][2] ^ w[1], R[0][3] ^ w[2],
                           R[1][1] ^ w[3], R[1][2] ^ w[4], R[1][3] ^ w[5],
                           R[2][1] ^ w[6], R[2][2] ^ w[7], R[2][3] ^ w[8]);
            int c2 = popc9(R[1][0] ^ w[0], R[1][1] ^ w[1], R[1][2] ^ w[2],
                           R[2][0] ^ w[3], R[2][1] ^ w[4], R[2][2] ^ w[5],
                           R[3][0] ^ w[6], R[3][1] ^ w[7], R[3][2] ^ w[8]);
            int c3 = popc9(R[1][1] ^ w[0], R[1][2] ^ w[1], R[1][3] ^ w[2],
                           R[2][1] ^ w[3], R[2][2] ^ w[4], R[2][3] ^ w[5],
                           R[3][1] ^ w[6], R[3][2] ^ w[7], R[3][3] ^ w[8]);
            int m = min(min(c0, c1), min(c2, c3));
            acc |= (m <= T) ? (1u << oc) : 0u;
        }
        pinw[r] = acc;                    // s2 staged into dead pin area (word r = pr*4+pc)
    }
    __syncwarp();

    // ---- conv3 (288-term, 64 oc; 4 per lane) + pool -> 64 bits (a0,a1) ----
    unsigned S2[16];
#pragma unroll
    for (int i = 0; i < 16; ++i) S2[i] = pinw[i];

    unsigned p = 0u;
    const int ocb3 = r * 4;
#pragma unroll 1
    for (int k = 0; k < 4; ++k) {
        int oc = ocb3 + k;
        unsigned w[9];
#pragma unroll
        for (int j = 0; j < 9; ++j) w[j] = __ldg(&g_w3[oc * 9 + j]);
        int T = __ldg(&g_T3[oc]);
        int c0 = popc9(S2[0] ^ w[0], S2[1] ^ w[1], S2[2] ^ w[2],
                       S2[4] ^ w[3], S2[5] ^ w[4], S2[6] ^ w[5],
                       S2[8] ^ w[6], S2[9] ^ w[7], S2[10] ^ w[8]);
        int c1 = popc9(S2[1] ^ w[0], S2[2] ^ w[1], S2[3] ^ w[2],
                       S2[5] ^ w[3], S2[6] ^ w[4], S2[7] ^ w[5],
                       S2[9] ^ w[6], S2[10] ^ w[7], S2[11] ^ w[8]);
        int c2 = popc9(S2[4] ^ w[0], S2[5] ^ w[1], S2[6] ^ w[2],
                       S2[8] ^ w[3], S2[9] ^ w[4], S2[10] ^ w[5],
                       S2[12] ^ w[6], S2[13] ^ w[7], S2[14] ^ w[8]);
        int c3 = popc9(S2[5] ^ w[0], S2[6] ^ w[1], S2[7] ^ w[2],
                       S2[9] ^ w[3], S2[10] ^ w[4], S2[11] ^ w[5],
                       S2[13] ^ w[6], S2[14] ^ w[7], S2[15] ^ w[8]);
        int m = min(min(c0, c1), min(c2, c3));
        p |= (m <= T) ? (1u << (oc & 31)) : 0u;
    }
    p |= __shfl_xor_sync(0xFFFFFFFFu, p, 1);
    p |= __shfl_xor_sync(0xFFFFFFFFu, p, 2);
    p |= __shfl_xor_sync(0xFFFFFFFFu, p, 4);
    unsigned other = __shfl_xor_sync(0xFFFFFFFFu, p, 8);
    unsigned a0 = (r & 8) ? other : p;
    unsigned a1 = (r & 8) ? p : other;

    // ---- fc1 (binary 64-dot) + bn4 + hardtanh + float heads (8 outputs per lane) ----
    float t0 = 0.f, t1 = 0.f, u0 = 0.f, u1 = 0.f, u2 = 0.f, u3 = 0.f;
    const int jb = r * 8;
    const float4* A4v = (const float4*)(g_a4 + jb);
    const float4* C4v = (const float4*)(g_c4 + jb);
    const float4* F2a = (const float4*)(wfc2 + jb);
    const float4* F2b = (const float4*)(wfc2 + 128 + jb);
    const float4* F3a = (const float4*)(wfc3 + jb);
    const float4* F3b = (const float4*)(wfc3 + 128 + jb);
    const float4* F3c = (const float4*)(wfc3 + 256 + jb);
    const float4* F3d = (const float4*)(wfc3 + 384 + jb);
    const uint2* FCW = (const uint2*)s_fc1;

#pragma unroll
    for (int q = 0; q < 2; ++q) {
        float4 a4v = __ldg(&A4v[q]);
        float4 c4v = __ldg(&C4v[q]);
        float4 f2a = __ldg(&F2a[q]);
        float4 f2b = __ldg(&F2b[q]);
        float4 f3a = __ldg(&F3a[q]);
        float4 f3b = __ldg(&F3b[q]);
        float4 f3c = __ldg(&F3c[q]);
        float4 f3d = __ldg(&F3d[q]);
#define FC1_STEP(comp, kk) do {                                             \
        uint2 fw = FCW[jb + 4 * q + (kk)];                                  \
        int cnt = __popc(a0 ^ fw.x) + __popc(a1 ^ fw.y);                    \
        float sv = (float)(64 - 2 * cnt);                                   \
        float h = fminf(1.f, fmaxf(-1.f, fmaf(sv, a4v.comp, c4v.comp)));    \
        t0 = fmaf(h, f2a.comp, t0);  t1 = fmaf(h, f2b.comp, t1);            \
        u0 = fmaf(h, f3a.comp, u0);  u1 = fmaf(h, f3b.comp, u1);            \
        u2 = fmaf(h, f3c.comp, u2);  u3 = fmaf(h, f3d.comp, u3); } while (0)
        FC1_STEP(x, 0);
        FC1_STEP(y, 1);
        FC1_STEP(z, 2);
        FC1_STEP(w, 3);
#undef FC1_STEP
    }
#pragma unroll
    for (int d = 1; d < 16; d <<= 1) {
        t0 += __shfl_xor_sync(0xFFFFFFFFu, t0, d);
        t1 += __shfl_xor_sync(0xFFFFFFFFu, t1, d);
        u0 += __shfl_xor_sync(0xFFFFFFFFu, u0, d);
        u1 += __shfl_xor_sync(0xFFFFFFFFu, u1, d);
        u2 += __shfl_xor_sync(0xFFFFFFFFu, u2, d);
        u3 += __shfl_xor_sync(0xFFFFFFFFu, u3, d);
    }
    if (r == 0) {
        float z0 = fmaf(t0, g_head[0], g_head[2]);
        float z1 = fmaf(t1, g_head[1], g_head[3]);
        float mx = fmaxf(z0, z1);
        float e0 = expf(z0 - mx), e1 = expf(z1 - mx);
        float is = 1.f / (e0 + e1);
        out[2 * s]     = e0 * is;
        out[2 * s + 1] = e1 * is;
        float* o2 = out + (size_t)2 * B;
        o2[4 * s]     = fmaf(u0, g_head[4], g_head[8]);
        o2[4 * s + 1] = fmaf(u1, g_head[5], g_head[9]);
        o2[4 * s + 2] = fmaf(u2, g_head[6], g_head[10]);
        o2[4 * s + 3] = fmaf(u3, g_head[7], g_head[11]);
    }
}

// ---------------- launch ----------------
extern "C" void kernel_launch(void* const* d_in, const int* in_sizes, int n_in,
                              void* d_out, int out_size) {
    (void)n_in; (void)out_size;
    const float* x    = (const float*)d_in[0];
    const float* w1   = (const float*)d_in[1];
    const float* w2   = (const float*)d_in[2];
    const float* w3   = (const float*)d_in[3];
    const float* wfc1 = (const float*)d_in[4];
    const float* wfc2 = (const float*)d_in[5];
    const float* wfc3 = (const float*)d_in[6];
    const float* bn1  = (const float*)d_in[7];
    const float* bn2  = (const float*)d_in[8];
    const float* bn3  = (const float*)d_in[9];
    const float* bn4  = (const float*)d_in[10];
    const float* bn5  = (const float*)d_in[11];
    const float* bn6  = (const float*)d_in[12];

    int B = in_sizes[0] / 1452;  // 3*22*22
    if (B > MAXB) B = MAXB;

    cudaFuncSetAttribute(main_kernel, cudaFuncAttributeMaxDynamicSharedMemorySize,
                         SM_WORDS * (int)sizeof(unsigned));

    prep_kernel<<<8, 256>>>(w1, w2, w3, wfc1, bn1, bn2, bn3, bn4, bn5, bn6);
    main_kernel<<<(B * 16 + 127) / 128, 128, SM_WORDS * sizeof(unsigned)>>>(
        x, wfc2, wfc3, (float*)d_out, B);
}

// round 12
// speedup vs baseline: 1.3619x; 1.0227x over previous
#include <cuda_runtime.h>
#include <math.h>

#define MAXB 16384

// ---------------- device scratch (no allocations allowed) ----------------
// LUT: A[1536 records]xuint4 (slots oc0..19) then B[1536]xuint2 (slots oc20..29)
__device__ __align__(16) unsigned g_lut[9216];
__device__ __align__(16) unsigned g_w2r[384];   // [oc*12]: w[0..8], T2, pad, pad
__device__ __align__(16) unsigned g_w3r[768];   // [oc*12]: w[0..8], T3, pad, pad
__device__ unsigned g_w1d[6];                   // ch words for oc30 (0..2), oc31 (3..5)
__device__ int      g_T1d[2];                   // T1 for oc30, oc31
__device__ __align__(16) unsigned g_fc1[256];   // [j*2 + half]
__device__ __align__(16) float g_a4[128];
__device__ __align__(16) float g_c4[128];
__device__ float g_head[12];

// ---------------- bn threshold helper ----------------
__device__ __forceinline__ double bn_thresh_t(const float* bn, int C, int c) {
    double g = bn[c], b = bn[C + c], m = bn[2 * C + c], v = bn[3 * C + c];
    return m - b * sqrt(v + 1e-5) / g;
}

// ---------------- prep: weight packing + thresholds + conv1 LUT (8 CTAs) ----------------
__global__ void prep_kernel(const float* __restrict__ w1, const float* __restrict__ w2,
                            const float* __restrict__ w3, const float* __restrict__ wfc1,
                            const float* __restrict__ bn1, const float* __restrict__ bn2,
                            const float* __restrict__ bn3, const float* __restrict__ bn4,
                            const float* __restrict__ bn5, const float* __restrict__ bn6) {
    __shared__ unsigned s_wc[96];   // [ch*32+oc]: 9-bit channel slice of w1
    __shared__ int      s_off[32];  // 31 - clamp(T1, -5, 31)

    const int t = blockIdx.x * 256 + threadIdx.x;
    const int nt = 8 * 256;

    if (threadIdx.x < 96) {
        int ch = threadIdx.x / 32, oc = threadIdx.x & 31;
        unsigned w = 0;
        for (int k = 0; k < 9; ++k)
            if (w1[oc * 27 + ch * 9 + k] >= 0.f) w |= 1u << k;
        s_wc[threadIdx.x] = w;
    }
    if (threadIdx.x < 32) {
        int oc = threadIdx.x;
        int T = (int)floor((27.0 - bn_thresh_t(bn1, 32, oc)) * 0.5);
        if (T < -5) T = -5;
        if (T > 31) T = 31;
        s_off[oc] = 31 - T;   // reject iff cnt + off >= 32
    }
    __syncthreads();

    // conv1 LUT: 1536 records, 6 words each (A: 4, B: 2) covering oc 0..29
    for (int i = t; i < 1536; i += nt) {
        int ch = i / 512, key = i & 511;
        unsigned wrd[6];
        for (int g = 0; g < 6; ++g) {
            unsigned word = 0;
            for (int j = 0; j < 5; ++j) {
                int oc = 5 * g + j;
                unsigned f = (unsigned)__popc((key ^ s_wc[ch * 32 + oc]) & 0x1FF);
                if (ch == 2) f += (unsigned)s_off[oc];
                word |= f << (6 * j);
            }
            wrd[g] = word;
        }
        g_lut[i * 4 + 0] = wrd[0];
        g_lut[i * 4 + 1] = wrd[1];
        g_lut[i * 4 + 2] = wrd[2];
        g_lut[i * 4 + 3] = wrd[3];
        g_lut[6144 + i * 2 + 0] = wrd[4];
        g_lut[6144 + i * 2 + 1] = wrd[5];
    }
    // direct weights/thresholds for oc 30, 31
    if (t < 6) g_w1d[t] = s_wc[(t % 3) * 32 + 30 + (t / 3)];
    if (t >= 8 && t < 10) {
        int q = t - 8;
        g_T1d[q] = (int)floor((27.0 - bn_thresh_t(bn1, 32, 30 + q)) * 0.5);
    }

    // conv2 weight records: 12 words per oc (w0..w8, T2, pad, pad)
    for (int i = t; i < 288; i += nt) {
        int oc = i / 9, p = i % 9; unsigned w = 0;
        for (int c = 0; c < 32; ++c) if (w2[(oc * 32 + c) * 9 + p] >= 0.f) w |= 1u << c;
        g_w2r[oc * 12 + p] = w;
    }
    for (int oc = t; oc < 32; oc += nt) {
        g_w2r[oc * 12 + 9]  = (unsigned)(int)floor((288.0 - bn_thresh_t(bn2, 32, oc)) * 0.5);
        g_w2r[oc * 12 + 10] = 0;
        g_w2r[oc * 12 + 11] = 0;
    }
    // conv3 weight records: 12 words per oc (w0..w8, T3, pad, pad)
    for (int i = t; i < 576; i += nt) {
        int oc = i / 9, p = i % 9; unsigned w = 0;
        for (int c = 0; c < 32; ++c) if (w3[(oc * 32 + c) * 9 + p] >= 0.f) w |= 1u << c;
        g_w3r[oc * 12 + p] = w;
    }
    for (int oc = t; oc < 64; oc += nt) {
        g_w3r[oc * 12 + 9]  = (unsigned)(int)floor((288.0 - bn_thresh_t(bn3, 64, oc)) * 0.5);
        g_w3r[oc * 12 + 10] = 0;
        g_w3r[oc * 12 + 11] = 0;
    }
    for (int i = t; i < 256; i += nt) {
        int j = i >> 1, h = i & 1; unsigned w = 0;
        for (int k = 0; k < 32; ++k) if (wfc1[j * 64 + h * 32 + k] >= 0.f) w |= 1u << k;
        g_fc1[i] = w;
    }
    for (int j = t; j < 128; j += nt) {
        float g = bn4[j], b = bn4[128 + j], m = bn4[256 + j], v = bn4[384 + j];
        float inv = g * rsqrtf(v + 1e-5f);
        g_a4[j] = inv; g_c4[j] = b - m * inv;
    }
    if (t < 2) {
        float g = bn5[t], b = bn5[2 + t], m = bn5[4 + t], v = bn5[6 + t];
        float inv = g * rsqrtf(v + 1e-5f);
        g_head[t] = inv; g_head[2 + t] = b - m * inv;
    }
    if (t >= 4 && t < 8) {
        int q = t - 4;
        float g = bn6[q], b = bn6[4 + q], m = bn6[8 + q], v = bn6[12 + q];
        float inv = g * rsqrtf(v + 1e-5f);
        g_head[4 + q] = inv; g_head[8 + q] = b - m * inv;
    }
}

// naive 9-word popcount sum
__device__ __forceinline__ int popc9(unsigned x0, unsigned x1, unsigned x2,
                                     unsigned x3, unsigned x4, unsigned x5,
                                     unsigned x6, unsigned x7, unsigned x8) {
    return __popc(x0) + __popc(x1) + __popc(x2)
         + __popc(x3) + __popc(x4) + __popc(x5)
         + __popc(x6) + __popc(x7) + __popc(x8);
}

// dynamic smem word offsets (256-thread CTA, 16 samples, 16 lanes/sample)
#define SM_LUTA 0                       // 6144 words (1536 uint4)
#define SM_LUTB 6144                    // 3072 words (1536 uint2)
#define SM_PIN  9216                    // 16*66 = 1056
#define SM_S1   10272                   // 16*100 = 1600
#define SM_W2   11872                   // 384
#define SM_W3   12256                   // 768
#define SM_FC1  13024                   // 256
#define SM_WORDS 13280                  // 53120 bytes

// ---------------- main fused network: 16 threads per sample, 16 samples/CTA ----------------
__global__ void __launch_bounds__(256, 3) main_kernel(
    const float* __restrict__ x,
    const float* __restrict__ wfc2, const float* __restrict__ wfc3,
    float* __restrict__ out, int B) {

    extern __shared__ unsigned sm[];
    unsigned* s_fc1 = sm + SM_FC1;

    const int tid = threadIdx.x;
    {   // vectorized fills
        const uint4* srcL = (const uint4*)g_lut;
        uint4* dstL = (uint4*)sm;
        for (int i = tid; i < 2304; i += 256) dstL[i] = srcL[i];
        const uint4* srcW = (const uint4*)g_w2r;
        uint4* dstW = (uint4*)(sm + SM_W2);
        for (int i = tid; i < 96; i += 256) dstW[i] = srcW[i];
        const uint4* srcW3 = (const uint4*)g_w3r;
        uint4* dstW3 = (uint4*)(sm + SM_W3);
        for (int i = tid; i < 192; i += 256) dstW3[i] = srcW3[i];
        const uint4* srcF = (const uint4*)g_fc1;
        uint4* dstF = (uint4*)(sm + SM_FC1);
        for (int i = tid; i < 64; i += 256) dstF[i] = srcF[i];
    }
    __syncthreads();

    const int lane = tid & 31;
    const int base = blockIdx.x * 16;

    // ---- binarize + pack: each warp packs its 2 samples (coalesced loads + ballot) ----
    for (int ss = 0; ss < 2; ++ss) {
        int slot = (tid >> 5) * 2 + ss;
        int samp = base + slot;
        if (samp >= B) break;                       // uniform within warp
        const float* xs = x + (size_t)samp * 1452;
        unsigned* dst = sm + SM_S1 + slot * 100;    // 46-word bitstream staging
        for (int j0 = 0; j0 < 46; j0 += 8) {
            float v[8];
#pragma unroll
            for (int k = 0; k < 8; ++k) {
                int idx = (j0 + k) * 32 + lane;
                v[k] = (idx < 1452) ? xs[idx] : -1.f;
            }
#pragma unroll
            for (int k = 0; k < 8; ++k) {
                unsigned b = __ballot_sync(0xFFFFFFFFu, v[k] >= 0.f);
                if (lane == k && (j0 + k) < 46) dst[j0 + k] = b;
            }
        }
    }
    __syncwarp();

    const int gt = blockIdx.x * 256 + tid;
    const int s = gt >> 4;        // sample
    const int r = gt & 15;        // lane within 16-group
    if (s >= B) return;           // B multiple of 16 -> whole warps exit together
    const int sl = tid >> 4;      // sample slot in CTA (0..15)

    unsigned* pinw = sm + SM_PIN + sl * 66;
    unsigned* s1   = sm + SM_S1 + sl * 100;

    // re-align bitstream to 22-bit row words
    {
        const unsigned* st = s1;
        for (int i = r; i < 66; i += 16) {
            int off = i * 22;
            pinw[i] = __funnelshift_r(st[off >> 5], st[(off >> 5) + 1], off & 31) & 0x3FFFFFu;
        }
    }
    __syncwarp();

    const uint4* __restrict__ LA = (const uint4*)(sm + SM_LUTA);
    const uint2* __restrict__ LB = (const uint2*)(sm + SM_LUTB);

    // direct oc30/31 weights + thresholds (uniform broadcast loads)
    unsigned wd0 = __ldg(&g_w1d[0]), wd1 = __ldg(&g_w1d[1]), wd2 = __ldg(&g_w1d[2]);
    unsigned wd3 = __ldg(&g_w1d[3]), wd4 = __ldg(&g_w1d[4]), wd5 = __ldg(&g_w1d[5]);
    int T30 = __ldg(&g_T1d[0]), T31 = __ldg(&g_T1d[1]);

    // ---- conv1: LUT (oc 0..29) + direct popc (oc 30,31) + pool -> s1[10][10] ----
    for (int py = 0; py < 10; ++py) {
        // lane owns cell (py,px) iff (py*10+px) % 16 == r  ->  px = (r + 6*py) & 15, if <10
        int px = (r + 6 * py) & 15;
        if (px >= 10) continue;
        unsigned rows[12];
#pragma unroll
        for (int c = 0; c < 3; ++c)
#pragma unroll
            for (int k = 0; k < 2; ++k) {
                uint2 rw = *(const uint2*)(pinw + c * 22 + 2 * py + 2 * k);
                rows[c * 4 + 2 * k] = rw.x;
                rows[c * 4 + 2 * k + 1] = rw.y;
            }

        unsigned Aw[6];
#pragma unroll
        for (int g = 0; g < 6; ++g) Aw[g] = 0xFFFFFFFFu;
        int m30 = 99, m31 = 99;
#pragma unroll
        for (int yy = 0; yy < 2; ++yy)
#pragma unroll
            for (int xx = 0; xx < 2; ++xx) {
                int x0 = 2 * px + xx;
                int k0 = (int)(((rows[0 + yy] >> x0) & 7u)
                             | (((rows[1 + yy] >> x0) & 7u) << 3)
                             | (((rows[2 + yy] >> x0) & 7u) << 6));
                int k1 = (int)(((rows[4 + yy] >> x0) & 7u)
                             | (((rows[5 + yy] >> x0) & 7u) << 3)
                             | (((rows[6 + yy] >> x0) & 7u) << 6));
                int k2 = (int)(((rows[8 + yy] >> x0) & 7u)
                             | (((rows[9 + yy] >> x0) & 7u) << 3)
                             | (((rows[10 + yy] >> x0) & 7u) << 6));
                uint4 a0 = LA[k0], a1 = LA[512 + k1], a2 = LA[1024 + k2];
                uint2 b0 = LB[k0], b1 = LB[512 + k1], b2 = LB[1024 + k2];
                Aw[0] &= a0.x + a1.x + a2.x;
                Aw[1] &= a0.y + a1.y + a2.y;
                Aw[2] &= a0.z + a1.z + a2.z;
                Aw[3] &= a0.w + a1.w + a2.w;
                Aw[4] &= b0.x + b1.x + b2.x;
                Aw[5] &= b0.y + b1.y + b2.y;
                int c30 = __popc((unsigned)k0 ^ wd0) + __popc((unsigned)k1 ^ wd1)
                        + __popc((unsigned)k2 ^ wd2);
                int c31 = __popc((unsigned)k0 ^ wd3) + __popc((unsigned)k1 ^ wd4)
                        + __popc((unsigned)k2 ^ wd5);
                m30 = min(m30, c30);
                m31 = min(m31, c31);
            }
        unsigned acc = 0;
#pragma unroll
        for (int g = 0; g < 6; ++g) {
            unsigned xb = (~Aw[g] & 0x20820820u) >> 5;   // keep bits at 0,6,12,18,24
            unsigned y = (xb * 0x108421u) >> 20;          // compress to 5 bits
            acc |= (y & 31u) << (5 * g);                  // oc 0..29
        }
        acc |= (m30 <= T30) ? (1u << 30) : 0u;
        acc |= (m31 <= T31) ? (1u << 31) : 0u;
        s1[py * 10 + px] = acc;
    }
    __syncwarp();

    // ---- conv2 (288-term): lane owns exactly 1 pooled cell (pr=r>>2, pc=r&3), all 32 oc ----
    {
        const int pr = r >> 2;
        const int pc = r & 3;
        unsigned R[4][4];                 // rows 2pr..2pr+3, cols 2pc..2pc+3
#pragma unroll
        for (int y = 0; y < 4; ++y)
#pragma unroll
            for (int xx = 0; xx < 4; ++xx) R[y][xx] = s1[(2 * pr + y) * 10 + 2 * pc + xx];
        unsigned acc = 0u;
        const uint4* W = (const uint4*)(sm + SM_W2);
#pragma unroll 2
        for (int oc = 0; oc < 32; ++oc) {
            uint4 wa = W[oc * 3 + 0];
            uint4 wb = W[oc * 3 + 1];
            uint4 wc = W[oc * 3 + 2];
            unsigned w[9] = {wa.x, wa.y, wa.z, wa.w, wb.x, wb.y, wb.z, wb.w, wc.x};
            int T = (int)wc.y;
            int c0 = popc9(R[0][0] ^ w[0], R[0][1] ^ w[1], R[0][2] ^ w[2],
                           R[1][0] ^ w[3], R[1][1] ^ w[4], R[1][2] ^ w[5],
                           R[2][0] ^ w[6], R[2][1] ^ w[7], R[2][2] ^ w[8]);
            int c1 = popc9(R[0][1] ^ w[0], R[0][2] ^ w[1], R[0][3] ^ w[2],
                           R[1][1] ^ w[3], R[1][2] ^ w[4], R[1][3] ^ w[5],
                           R[2][1] ^ w[6], R[2][2] ^ w[7], R[2][3] ^ w[8]);
            int c2 = popc9(R[1][0] ^ w[0], R[1][1] ^ w[1], R[1][2] ^ w[2],
                           R[2][0] ^ w[3], R[2][1] ^ w[4], R[2][2] ^ w[5],
                           R[3][0] ^ w[6], R[3][1] ^ w[7], R[3][2] ^ w[8]);
            int c3 = popc9(R[1][1] ^ w[0], R[1][2] ^ w[1], R[1][3] ^ w[2],
                           R[2][1] ^ w[3], R[2][2] ^ w[4], R[2][3] ^ w[5],
                           R[3][1] ^ w[6], R[3][2] ^ w[7], R[3][3] ^ w[8]);
            int m = min(min(c0, c1), min(c2, c3));
            acc |= (m <= T) ? (1u << oc) : 0u;
        }
        pinw[r] = acc;                    // s2 staged into dead pin area (word r = pr*4+pc)
    }
    __syncwarp();

    // ---- conv3 (288-term, 64 oc; 4 per lane, weights in smem) + pool -> 64 bits ----
    unsigned S2[16];
#pragma unroll
    for (int i = 0; i < 16; ++i) S2[i] = pinw[i];

    unsigned p = 0u;
    const int ocb3 = r * 4;
    const uint4* W3 = (const uint4*)(sm + SM_W3);
#pragma unroll 1
    for (int k = 0; k < 4; ++k) {
        int oc = ocb3 + k;
        uint4 wa = W3[oc * 3 + 0];
        uint4 wb = W3[oc * 3 + 1];
        uint4 wc = W3[oc * 3 + 2];
        unsigned w[9] = {wa.x, wa.y, wa.z, wa.w, wb.x, wb.y, wb.z, wb.w, wc.x};
        int T = (int)wc.y;
        int c0 = popc9(S2[0] ^ w[0], S2[1] ^ w[1], S2[2] ^ w[2],
                       S2[4] ^ w[3], S2[5] ^ w[4], S2[6] ^ w[5],
                       S2[8] ^ w[6], S2[9] ^ w[7], S2[10] ^ w[8]);
        int c1 = popc9(S2[1] ^ w[0], S2[2] ^ w[1], S2[3] ^ w[2],
                       S2[5] ^ w[3], S2[6] ^ w[4], S2[7] ^ w[5],
                       S2[9] ^ w[6], S2[10] ^ w[7], S2[11] ^ w[8]);
        int c2 = popc9(S2[4] ^ w[0], S2[5] ^ w[1], S2[6] ^ w[2],
                       S2[8] ^ w[3], S2[9] ^ w[4], S2[10] ^ w[5],
                       S2[12] ^ w[6], S2[13] ^ w[7], S2[14] ^ w[8]);
        int c3 = popc9(S2[5] ^ w[0], S2[6] ^ w[1], S2[7] ^ w[2],
                       S2[9] ^ w[3], S2[10] ^ w[4], S2[11] ^ w[5],
                       S2[13] ^ w[6], S2[14] ^ w[7], S2[15] ^ w[8]);
        int m = min(min(c0, c1), min(c2, c3));
        p |= (m <= T) ? (1u << (oc & 31)) : 0u;
    }
    p |= __shfl_xor_sync(0xFFFFFFFFu, p, 1);
    p |= __shfl_xor_sync(0xFFFFFFFFu, p, 2);
    p |= __shfl_xor_sync(0xFFFFFFFFu, p, 4);
    unsigned other = __shfl_xor_sync(0xFFFFFFFFu, p, 8);
    unsigned a0 = (r & 8) ? other : p;
    unsigned a1 = (r & 8) ? p : other;

    // ---- fc1 (binary 64-dot) + bn4 + hardtanh + float heads (8 outputs per lane) ----
    float t0 = 0.f, t1 = 0.f, u0 = 0.f, u1 = 0.f, u2 = 0.f, u3 = 0.f;
    const int jb = r * 8;
    const float4* A4v = (const float4*)(g_a4 + jb);
    const float4* C4v = (const float4*)(g_c4 + jb);
    const float4* F2a = (const float4*)(wfc2 + jb);
    const float4* F2b = (const float4*)(wfc2 + 128 + jb);
    const float4* F3a = (const float4*)(wfc3 + jb);
    const float4* F3b = (const float4*)(wfc3 + 128 + jb);
    const float4* F3c = (const float4*)(wfc3 + 256 + jb);
    const float4* F3d = (const float4*)(wfc3 + 384 + jb);
    const uint2* FCW = (const uint2*)s_fc1;

#pragma unroll
    for (int q = 0; q < 2; ++q) {
        float4 a4v = __ldg(&A4v[q]);
        float4 c4v = __ldg(&C4v[q]);
        float4 f2a = __ldg(&F2a[q]);
        float4 f2b = __ldg(&F2b[q]);
        float4 f3a = __ldg(&F3a[q]);
        float4 f3b = __ldg(&F3b[q]);
        float4 f3c = __ldg(&F3c[q]);
        float4 f3d = __ldg(&F3d[q]);
#define FC1_STEP(comp, kk) do {                                             \
        uint2 fw = FCW[jb + 4 * q + (kk)];                                  \
        int cnt = __popc(a0 ^ fw.x) + __popc(a1 ^ fw.y);                    \
        float sv = (float)(64 - 2 * cnt);                                   \
        float h = fminf(1.f, fmaxf(-1.f, fmaf(sv, a4v.comp, c4v.comp)));    \
        t0 = fmaf(h, f2a.comp, t0);  t1 = fmaf(h, f2b.comp, t1);            \
        u0 = fmaf(h, f3a.comp, u0);  u1 = fmaf(h, f3b.comp, u1);            \
        u2 = fmaf(h, f3c.comp, u2);  u3 = fmaf(h, f3d.comp, u3); } while (0)
        FC1_STEP(x, 0);
        FC1_STEP(y, 1);
        FC1_STEP(z, 2);
        FC1_STEP(w, 3);
#undef FC1_STEP
    }
#pragma unroll
    for (int d = 1; d < 16; d <<= 1) {
        t0 += __shfl_xor_sync(0xFFFFFFFFu, t0, d);
        t1 += __shfl_xor_sync(0xFFFFFFFFu, t1, d);
        u0 += __shfl_xor_sync(0xFFFFFFFFu, u0, d);
        u1 += __shfl_xor_sync(0xFFFFFFFFu, u1, d);
        u2 += __shfl_xor_sync(0xFFFFFFFFu, u2, d);
        u3 += __shfl_xor_sync(0xFFFFFFFFu, u3, d);
    }
    if (r == 0) {
        float z0 = fmaf(t0, g_head[0], g_head[2]);
        float z1 = fmaf(t1, g_head[1], g_head[3]);
        float mx = fmaxf(z0, z1);
        float e0 = expf(z0 - mx), e1 = expf(z1 - mx);
        float is = 1.f / (e0 + e1);
        out[2 * s]     = e0 * is;
        out[2 * s + 1] = e1 * is;
        float* o2 = out + (size_t)2 * B;
        o2[4 * s]     = fmaf(u0, g_head[4], g_head[8]);
        o2[4 * s + 1] = fmaf(u1, g_head[5], g_head[9]);
        o2[4 * s + 2] = fmaf(u2, g_head[6], g_head[10]);
        o2[4 * s + 3] = fmaf(u3, g_head[7], g_head[11]);
    }
}

// ---------------- launch ----------------
extern "C" void kernel_launch(void* const* d_in, const int* in_sizes, int n_in,
                              void* d_out, int out_size) {
    (void)n_in; (void)out_size;
    const float* x    = (const float*)d_in[0];
    const float* w1   = (const float*)d_in[1];
    const float* w2   = (const float*)d_in[2];
    const float* w3   = (const float*)d_in[3];
    const float* wfc1 = (const float*)d_in[4];
    const float* wfc2 = (const float*)d_in[5];
    const float* wfc3 = (const float*)d_in[6];
    const float* bn1  = (const float*)d_in[7];
    const float* bn2  = (const float*)d_in[8];
    const float* bn3  = (const float*)d_in[9];
    const float* bn4  = (const float*)d_in[10];
    const float* bn5  = (const float*)d_in[11];
    const float* bn6  = (const float*)d_in[12];

    int B = in_sizes[0] / 1452;  // 3*22*22
    if (B > MAXB) B = MAXB;

    cudaFuncSetAttribute(main_kernel, cudaFuncAttributeMaxDynamicSharedMemorySize,
                         SM_WORDS * (int)sizeof(unsigned));

    prep_kernel<<<8, 256>>>(w1, w2, w3, wfc1, bn1, bn2, bn3, bn4, bn5, bn6);
    main_kernel<<<(B * 16 + 255) / 256, 256, SM_WORDS * sizeof(unsigned)>>>(
        x, wfc2, wfc3, (float*)d_out, B);
}